// round 5
// baseline (speedup 1.0000x reference)
#include <cuda_runtime.h>
#include <cuda_bf16.h>
#include <math_constants.h>

// Problem dims
#define BB 8
#define S1 2048
#define S2 2048
#define KD 512      // K1_DIM == K2_DIM
#define PKD 256     // PK1_DIM == PK2_DIM
#define AD 512      // ATT_DIM
#define DV 512

// GEMM tile config
#define BM 128
#define BN 128
#define BKK 16

// Scratch for projected tensors (allowed: __device__ globals, no allocation)
__device__ float g_k1p[BB * S1 * AD];
__device__ float g_k2p[BB * S2 * AD];
__device__ float g_pk1[BB * S1 * AD];
__device__ float g_pk2[BB * S2 * AD];

// ---------------------------------------------------------------------------
// Dtype-robust length read. Lengths are in [S/2, S) so strictly positive and
// < 2^31. If the harness stored them as int64 (little-endian), the int32 view
// is [l0, 0, l1, 0, ...] -> arr[1] == 0. If int32, arr[1] is a length != 0.
// ---------------------------------------------------------------------------
__device__ __forceinline__ int read_len(const int* __restrict__ arr, int b) {
    return (arr[1] == 0) ? arr[2 * b] : arr[b];
}

// ---------------------------------------------------------------------------
// NN GEMM: C[m,n] = sum_k A[m,k] * B[k,n] (+ bias[n]); batched via blockIdx.z
// All dims assumed multiples of tile sizes (true for this problem).
// ---------------------------------------------------------------------------
__global__ __launch_bounds__(256) void sgemm_nn(
    const float* __restrict__ A, long long sA,
    const float* __restrict__ B, long long sB,
    const float* __restrict__ bias,
    float* __restrict__ C, long long sC,
    int M, int N, int K)
{
    A += (long long)blockIdx.z * sA;
    B += (long long)blockIdx.z * sB;
    C += (long long)blockIdx.z * sC;

    __shared__ float As[BKK][BM];
    __shared__ float Bs[BKK][BN];

    const int tid = threadIdx.x;
    const int tx = tid & 15;
    const int ty = tid >> 4;
    const int row0 = blockIdx.y * BM;
    const int col0 = blockIdx.x * BN;

    float acc[8][8];
#pragma unroll
    for (int i = 0; i < 8; i++)
#pragma unroll
        for (int j = 0; j < 8; j++) acc[i][j] = 0.f;

    for (int k0 = 0; k0 < K; k0 += BKK) {
        // A tile: 128x16 = 512 float4s, 2 per thread, stored transposed
#pragma unroll
        for (int i = 0; i < 2; i++) {
            int f = tid + i * 256;
            int r = f >> 2;
            int c4 = (f & 3) * 4;
            float4 v = *(const float4*)(A + (long long)(row0 + r) * K + k0 + c4);
            As[c4 + 0][r] = v.x; As[c4 + 1][r] = v.y;
            As[c4 + 2][r] = v.z; As[c4 + 3][r] = v.w;
        }
        // B tile: 16x128
#pragma unroll
        for (int i = 0; i < 2; i++) {
            int f = tid + i * 256;
            int r = f >> 5;
            int c4 = (f & 31) * 4;
            *(float4*)&Bs[r][c4] = *(const float4*)(B + (long long)(k0 + r) * N + col0 + c4);
        }
        __syncthreads();
#pragma unroll
        for (int k = 0; k < BKK; k++) {
            float4 a0 = *(float4*)&As[k][ty * 4];
            float4 a1 = *(float4*)&As[k][64 + ty * 4];
            float4 b0 = *(float4*)&Bs[k][tx * 4];
            float4 b1 = *(float4*)&Bs[k][64 + tx * 4];
            float a[8] = {a0.x, a0.y, a0.z, a0.w, a1.x, a1.y, a1.z, a1.w};
            float b[8] = {b0.x, b0.y, b0.z, b0.w, b1.x, b1.y, b1.z, b1.w};
#pragma unroll
            for (int i = 0; i < 8; i++)
#pragma unroll
                for (int j = 0; j < 8; j++) acc[i][j] += a[i] * b[j];
        }
        __syncthreads();
    }

#pragma unroll
    for (int ih = 0; ih < 2; ih++)
#pragma unroll
        for (int ii = 0; ii < 4; ii++) {
            int r = row0 + ih * 64 + ty * 4 + ii;
#pragma unroll
            for (int jh = 0; jh < 2; jh++) {
                int c = col0 + jh * 64 + tx * 4;
                float4 v;
                v.x = acc[ih * 4 + ii][jh * 4 + 0];
                v.y = acc[ih * 4 + ii][jh * 4 + 1];
                v.z = acc[ih * 4 + ii][jh * 4 + 2];
                v.w = acc[ih * 4 + ii][jh * 4 + 3];
                if (bias) {
                    v.x += bias[c + 0]; v.y += bias[c + 1];
                    v.z += bias[c + 2]; v.w += bias[c + 3];
                }
                *(float4*)(C + (long long)r * N + c) = v;
            }
        }
}

// ---------------------------------------------------------------------------
// NT GEMM: C[m,n] = sum_k A[m,k] * B[n,k]; batched via blockIdx.z
// ---------------------------------------------------------------------------
__global__ __launch_bounds__(256) void sgemm_nt(
    const float* __restrict__ A, long long sA,
    const float* __restrict__ B, long long sB,
    float* __restrict__ C, long long sC,
    int M, int N, int K)
{
    A += (long long)blockIdx.z * sA;
    B += (long long)blockIdx.z * sB;
    C += (long long)blockIdx.z * sC;

    __shared__ float As[BKK][BM];
    __shared__ float Bs[BKK][BN];

    const int tid = threadIdx.x;
    const int tx = tid & 15;
    const int ty = tid >> 4;
    const int row0 = blockIdx.y * BM;
    const int col0 = blockIdx.x * BN;

    float acc[8][8];
#pragma unroll
    for (int i = 0; i < 8; i++)
#pragma unroll
        for (int j = 0; j < 8; j++) acc[i][j] = 0.f;

    for (int k0 = 0; k0 < K; k0 += BKK) {
#pragma unroll
        for (int i = 0; i < 2; i++) {
            int f = tid + i * 256;
            int r = f >> 2;
            int c4 = (f & 3) * 4;
            float4 v = *(const float4*)(A + (long long)(row0 + r) * K + k0 + c4);
            As[c4 + 0][r] = v.x; As[c4 + 1][r] = v.y;
            As[c4 + 2][r] = v.z; As[c4 + 3][r] = v.w;
        }
        // B is [N,K] row-major; load 128 (n) x 16 (k), store transposed
#pragma unroll
        for (int i = 0; i < 2; i++) {
            int f = tid + i * 256;
            int n = f >> 2;
            int c4 = (f & 3) * 4;
            float4 v = *(const float4*)(B + (long long)(col0 + n) * K + k0 + c4);
            Bs[c4 + 0][n] = v.x; Bs[c4 + 1][n] = v.y;
            Bs[c4 + 2][n] = v.z; Bs[c4 + 3][n] = v.w;
        }
        __syncthreads();
#pragma unroll
        for (int k = 0; k < BKK; k++) {
            float4 a0 = *(float4*)&As[k][ty * 4];
            float4 a1 = *(float4*)&As[k][64 + ty * 4];
            float4 b0 = *(float4*)&Bs[k][tx * 4];
            float4 b1 = *(float4*)&Bs[k][64 + tx * 4];
            float a[8] = {a0.x, a0.y, a0.z, a0.w, a1.x, a1.y, a1.z, a1.w};
            float b[8] = {b0.x, b0.y, b0.z, b0.w, b1.x, b1.y, b1.z, b1.w};
#pragma unroll
            for (int i = 0; i < 8; i++)
#pragma unroll
                for (int j = 0; j < 8; j++) acc[i][j] += a[i] * b[j];
        }
        __syncthreads();
    }

#pragma unroll
    for (int ih = 0; ih < 2; ih++)
#pragma unroll
        for (int ii = 0; ii < 4; ii++) {
            int r = row0 + ih * 64 + ty * 4 + ii;
#pragma unroll
            for (int jh = 0; jh < 2; jh++) {
                int c = col0 + jh * 64 + tx * 4;
                float4 v;
                v.x = acc[ih * 4 + ii][jh * 4 + 0];
                v.y = acc[ih * 4 + ii][jh * 4 + 1];
                v.z = acc[ih * 4 + ii][jh * 4 + 2];
                v.w = acc[ih * 4 + ii][jh * 4 + 3];
                *(float4*)(C + (long long)r * N + c) = v;
            }
        }
}

// ---------------------------------------------------------------------------
// Concat-A NN GEMM: A = [A1 | A2] along K (K1 + K2 columns), used for pk proj.
// M = BB*S, N = AD. K1, K2 multiples of BKK.
// ---------------------------------------------------------------------------
__global__ __launch_bounds__(256) void sgemm_nn_concat(
    const float* __restrict__ A1, int K1,
    const float* __restrict__ A2, int K2,
    const float* __restrict__ B,
    const float* __restrict__ bias,
    float* __restrict__ C,
    int M, int N)
{
    const int K = K1 + K2;
    __shared__ float As[BKK][BM];
    __shared__ float Bs[BKK][BN];

    const int tid = threadIdx.x;
    const int tx = tid & 15;
    const int ty = tid >> 4;
    const int row0 = blockIdx.y * BM;
    const int col0 = blockIdx.x * BN;

    float acc[8][8];
#pragma unroll
    for (int i = 0; i < 8; i++)
#pragma unroll
        for (int j = 0; j < 8; j++) acc[i][j] = 0.f;

    for (int k0 = 0; k0 < K; k0 += BKK) {
        const float* Ap; int ld, kk;
        if (k0 < K1) { Ap = A1; ld = K1; kk = k0; }
        else         { Ap = A2; ld = K2; kk = k0 - K1; }
#pragma unroll
        for (int i = 0; i < 2; i++) {
            int f = tid + i * 256;
            int r = f >> 2;
            int c4 = (f & 3) * 4;
            float4 v = *(const float4*)(Ap + (long long)(row0 + r) * ld + kk + c4);
            As[c4 + 0][r] = v.x; As[c4 + 1][r] = v.y;
            As[c4 + 2][r] = v.z; As[c4 + 3][r] = v.w;
        }
#pragma unroll
        for (int i = 0; i < 2; i++) {
            int f = tid + i * 256;
            int r = f >> 5;
            int c4 = (f & 31) * 4;
            *(float4*)&Bs[r][c4] = *(const float4*)(B + (long long)(k0 + r) * N + col0 + c4);
        }
        __syncthreads();
#pragma unroll
        for (int k = 0; k < BKK; k++) {
            float4 a0 = *(float4*)&As[k][ty * 4];
            float4 a1 = *(float4*)&As[k][64 + ty * 4];
            float4 b0 = *(float4*)&Bs[k][tx * 4];
            float4 b1 = *(float4*)&Bs[k][64 + tx * 4];
            float a[8] = {a0.x, a0.y, a0.z, a0.w, a1.x, a1.y, a1.z, a1.w};
            float b[8] = {b0.x, b0.y, b0.z, b0.w, b1.x, b1.y, b1.z, b1.w};
#pragma unroll
            for (int i = 0; i < 8; i++)
#pragma unroll
                for (int j = 0; j < 8; j++) acc[i][j] += a[i] * b[j];
        }
        __syncthreads();
    }

#pragma unroll
    for (int ih = 0; ih < 2; ih++)
#pragma unroll
        for (int ii = 0; ii < 4; ii++) {
            int r = row0 + ih * 64 + ty * 4 + ii;
#pragma unroll
            for (int jh = 0; jh < 2; jh++) {
                int c = col0 + jh * 64 + tx * 4;
                float4 v;
                v.x = acc[ih * 4 + ii][jh * 4 + 0] + bias[c + 0];
                v.y = acc[ih * 4 + ii][jh * 4 + 1] + bias[c + 1];
                v.z = acc[ih * 4 + ii][jh * 4 + 2] + bias[c + 2];
                v.w = acc[ih * 4 + ii][jh * 4 + 3] + bias[c + 3];
                *(float4*)(C + (long long)r * N + c) = v;
            }
        }
}

// ---------------------------------------------------------------------------
// Masked in-place row softmax over W[B, Rdim, Cdim].
// Position (r,c) masked iff EXACTLY ONE of (r >= lenR[b]) / (c >= lenC[b]).
// One block per row; 256 threads x 8 elements = 2048 columns.
// lenR/lenC passed as int32 views; read_len handles int32-or-int64 storage.
// ---------------------------------------------------------------------------
__global__ __launch_bounds__(256) void softmax_mask_kernel(
    float* __restrict__ W, int Rdim, int Cdim,
    const int* __restrict__ lenR, const int* __restrict__ lenC)
{
    const int b = blockIdx.y;
    const int r = blockIdx.x;
    float* row = W + ((long long)b * Rdim + r) * (long long)Cdim;
    const int lc = read_len(lenC, b);
    const bool rover = r >= read_len(lenR, b);
    const int tid = threadIdx.x;
    const int c0 = tid * 8;

    float vals[8];
    float4 v0 = *(float4*)(row + c0);
    float4 v1 = *(float4*)(row + c0 + 4);
    vals[0] = v0.x; vals[1] = v0.y; vals[2] = v0.z; vals[3] = v0.w;
    vals[4] = v1.x; vals[5] = v1.y; vals[6] = v1.z; vals[7] = v1.w;

    float m = -CUDART_INF_F;
#pragma unroll
    for (int i = 0; i < 8; i++) {
        bool cover = (c0 + i) >= lc;
        if (cover != rover) vals[i] = -CUDART_INF_F;   // XOR mask semantics
        m = fmaxf(m, vals[i]);
    }

    const int lane = tid & 31, wid = tid >> 5;
    __shared__ float smax[8];
    __shared__ float ssum[8];
#pragma unroll
    for (int o = 16; o; o >>= 1) m = fmaxf(m, __shfl_xor_sync(0xffffffffu, m, o));
    if (!lane) smax[wid] = m;
    __syncthreads();
    m = smax[0];
#pragma unroll
    for (int i = 1; i < 8; i++) m = fmaxf(m, smax[i]);

    float s = 0.f;
#pragma unroll
    for (int i = 0; i < 8; i++) {
        vals[i] = __expf(vals[i] - m);   // exp(-inf) = 0
        s += vals[i];
    }
#pragma unroll
    for (int o = 16; o; o >>= 1) s += __shfl_xor_sync(0xffffffffu, s, o);
    if (!lane) ssum[wid] = s;
    __syncthreads();
    s = ssum[0];
#pragma unroll
    for (int i = 1; i < 8; i++) s += ssum[i];
    float inv = 1.f / s;

    v0.x = vals[0] * inv; v0.y = vals[1] * inv; v0.z = vals[2] * inv; v0.w = vals[3] * inv;
    v1.x = vals[4] * inv; v1.y = vals[5] * inv; v1.z = vals[6] * inv; v1.w = vals[7] * inv;
    *(float4*)(row + c0) = v0;
    *(float4*)(row + c0 + 4) = v1;
}

// ---------------------------------------------------------------------------
// Launch
// ---------------------------------------------------------------------------
extern "C" void kernel_launch(void* const* d_in, const int* in_sizes, int n_in,
                              void* d_out, int out_size)
{
    const float* k1   = (const float*)d_in[0];
    const float* k2   = (const float*)d_in[1];
    const float* pk1c = (const float*)d_in[2];   // preserved_k1
    const float* pk2c = (const float*)d_in[3];   // preserved_k2
    const float* v1   = (const float*)d_in[4];
    const float* v2   = (const float*)d_in[5];
    const float* W_k1  = (const float*)d_in[6];
    const float* b_k1  = (const float*)d_in[7];
    const float* W_k2  = (const float*)d_in[8];
    const float* b_k2  = (const float*)d_in[9];
    const float* W_pk1 = (const float*)d_in[10];
    const float* b_pk1 = (const float*)d_in[11];
    const float* W_pk2 = (const float*)d_in[12];
    const float* b_pk2 = (const float*)d_in[13];
    const int* l1 = (const int*)d_in[14];  // k1_lengths (int32 or int64 storage)
    const int* l2 = (const int*)d_in[15];  // k2_lengths

    // Output layout (reference tuple order): o1, o2, w1, w2
    float* o1 = (float*)d_out;                                   // [B,S2,DV]
    float* o2 = o1 + (long long)BB * S2 * DV;                    // [B,S1,DV]
    float* w1 = o2 + (long long)BB * S1 * DV;                    // [B,S2,S1]
    float* w2 = w1 + (long long)BB * S2 * S1;                    // [B,S1,S2]

    float *gk1p, *gk2p, *gpk1, *gpk2;
    cudaGetSymbolAddress((void**)&gk1p, g_k1p);
    cudaGetSymbolAddress((void**)&gk2p, g_k2p);
    cudaGetSymbolAddress((void**)&gpk1, g_pk1);
    cudaGetSymbolAddress((void**)&gpk2, g_pk2);

    const int Mproj = BB * S1;   // 16384 (== BB*S2)

    // Projections (batch folded into M; weights shared)
    sgemm_nn<<<dim3(AD / BN, Mproj / BM, 1), 256>>>(
        k1, 0, W_k1, 0, b_k1, gk1p, 0, Mproj, AD, KD);
    sgemm_nn<<<dim3(AD / BN, Mproj / BM, 1), 256>>>(
        k2, 0, W_k2, 0, b_k2, gk2p, 0, Mproj, AD, KD);
    sgemm_nn_concat<<<dim3(AD / BN, Mproj / BM, 1), 256>>>(
        k1, KD, pk1c, PKD, W_pk1, b_pk1, gpk1, Mproj, AD);
    sgemm_nn_concat<<<dim3(AD / BN, Mproj / BM, 1), 256>>>(
        k2, KD, pk2c, PKD, W_pk2, b_pk2, gpk2, Mproj, AD);

    // Scores, written directly into the w output regions:
    //   w1_pre[b,t,s] = pk2[b,t,:] . k1p[b,s,:]   (= score_1^T)
    //   w2_pre[b,s,t] = pk1[b,s,:] . k2p[b,t,:]   (= score_2)
    sgemm_nt<<<dim3(S1 / BN, S2 / BM, BB), 256>>>(
        gpk2, (long long)S2 * AD, gk1p, (long long)S1 * AD,
        w1, (long long)S2 * S1, S2, S1, AD);
    sgemm_nt<<<dim3(S2 / BN, S1 / BM, BB), 256>>>(
        gpk1, (long long)S1 * AD, gk2p, (long long)S2 * AD,
        w2, (long long)S1 * S2, S1, S2, AD);

    // Masked softmax in place (mask: exactly-one-of / XOR semantics)
    softmax_mask_kernel<<<dim3(S2, BB), 256>>>(w1, S2, S1, l2, l1);
    softmax_mask_kernel<<<dim3(S1, BB), 256>>>(w2, S1, S2, l1, l2);

    // Outputs: o1 = w1 @ v1  [S2,S1]x[S1,DV];  o2 = w2 @ v2
    sgemm_nn<<<dim3(DV / BN, S2 / BM, BB), 256>>>(
        w1, (long long)S2 * S1, v1, (long long)S1 * DV, nullptr,
        o1, (long long)S2 * DV, S2, DV, S1);
    sgemm_nn<<<dim3(DV / BN, S1 / BM, BB), 256>>>(
        w2, (long long)S1 * S2, v2, (long long)S2 * DV, nullptr,
        o2, (long long)S1 * DV, S1, DV, S2);
}

// round 7
// speedup vs baseline: 2.5248x; 2.5248x over previous
#include <cuda_runtime.h>
#include <cuda_bf16.h>
#include <math_constants.h>
#include <cstdint>

// Problem dims
#define BB 8
#define SS 2048      // S1 == S2
#define KD 512       // K1_DIM == K2_DIM
#define PKD 256
#define CATD 768     // KD + PKD
#define AD 512       // ATT_DIM
#define DV 512

// ===========================================================================
// bf16 split scratch (static __device__ — allocation-free). 16B aligned for
// cp.async / vector loads.
// ===========================================================================
__device__ __align__(16) __nv_bfloat16 g_cat1_h[BB * SS * CATD];
__device__ __align__(16) __nv_bfloat16 g_cat1_l[BB * SS * CATD];
__device__ __align__(16) __nv_bfloat16 g_cat2_h[BB * SS * CATD];
__device__ __align__(16) __nv_bfloat16 g_cat2_l[BB * SS * CATD];

__device__ __align__(16) __nv_bfloat16 g_k1p_h[BB * SS * AD];
__device__ __align__(16) __nv_bfloat16 g_k1p_l[BB * SS * AD];
__device__ __align__(16) __nv_bfloat16 g_k2p_h[BB * SS * AD];
__device__ __align__(16) __nv_bfloat16 g_k2p_l[BB * SS * AD];
__device__ __align__(16) __nv_bfloat16 g_pk1_h[BB * SS * AD];
__device__ __align__(16) __nv_bfloat16 g_pk1_l[BB * SS * AD];
__device__ __align__(16) __nv_bfloat16 g_pk2_h[BB * SS * AD];
__device__ __align__(16) __nv_bfloat16 g_pk2_l[BB * SS * AD];

__device__ __align__(16) __nv_bfloat16 g_wtk1_h[AD * KD];
__device__ __align__(16) __nv_bfloat16 g_wtk1_l[AD * KD];
__device__ __align__(16) __nv_bfloat16 g_wtk2_h[AD * KD];
__device__ __align__(16) __nv_bfloat16 g_wtk2_l[AD * KD];
__device__ __align__(16) __nv_bfloat16 g_wtpk1_h[AD * CATD];
__device__ __align__(16) __nv_bfloat16 g_wtpk1_l[AD * CATD];
__device__ __align__(16) __nv_bfloat16 g_wtpk2_h[AD * CATD];
__device__ __align__(16) __nv_bfloat16 g_wtpk2_l[AD * CATD];

__device__ __align__(16) __nv_bfloat16 g_vt1_h[BB * DV * SS];
__device__ __align__(16) __nv_bfloat16 g_vt1_l[BB * DV * SS];
__device__ __align__(16) __nv_bfloat16 g_vt2_h[BB * DV * SS];
__device__ __align__(16) __nv_bfloat16 g_vt2_l[BB * DV * SS];

__device__ __align__(16) __nv_bfloat16 g_w1_h[BB * SS * SS];
__device__ __align__(16) __nv_bfloat16 g_w1_l[BB * SS * SS];
__device__ __align__(16) __nv_bfloat16 g_w2_h[BB * SS * SS];
__device__ __align__(16) __nv_bfloat16 g_w2_l[BB * SS * SS];

// ===========================================================================
// Helpers
// ===========================================================================
__device__ __forceinline__ uint32_t smem_u32(const void* p) {
    uint32_t a;
    asm("{ .reg .u64 t; cvta.to.shared.u64 t, %1; cvt.u32.u64 %0, t; }"
        : "=r"(a) : "l"(p));
    return a;
}

#define CP16(dst, src) \
    asm volatile("cp.async.cg.shared.global [%0], [%1], 16;" :: "r"(dst), "l"(src))
#define CP_COMMIT() asm volatile("cp.async.commit_group;" ::: "memory")
#define CP_WAIT1()  asm volatile("cp.async.wait_group 1;" ::: "memory")

#define LDSM_X4(r0, r1, r2, r3, addr) \
    asm volatile("ldmatrix.sync.aligned.m8n8.x4.shared.b16 {%0,%1,%2,%3}, [%4];" \
                 : "=r"(r0), "=r"(r1), "=r"(r2), "=r"(r3) : "r"(addr))

#define MMA16816(c, a, b0, b1) \
    asm volatile("mma.sync.aligned.m16n8k16.row.col.f32.bf16.bf16.f32 " \
                 "{%0,%1,%2,%3}, {%4,%5,%6,%7}, {%8,%9}, {%0,%1,%2,%3};" \
                 : "+f"((c)[0]), "+f"((c)[1]), "+f"((c)[2]), "+f"((c)[3]) \
                 : "r"((a)[0]), "r"((a)[1]), "r"((a)[2]), "r"((a)[3]), \
                   "r"(b0), "r"(b1))

__device__ __forceinline__ void split2(float x, __nv_bfloat16& h, __nv_bfloat16& l) {
    h = __float2bfloat16(x);
    l = __float2bfloat16(x - __bfloat162float(h));
}
__device__ __forceinline__ uint32_t pack_bf(__nv_bfloat16 a, __nv_bfloat16 b) {
    return ((uint32_t)__bfloat16_as_ushort(b) << 16) | (uint32_t)__bfloat16_as_ushort(a);
}

// Dtype-robust length read (lengths in [S/2,S); int64 LE view has arr[1]==0)
__device__ __forceinline__ int read_len(const int* __restrict__ arr, int b) {
    return (arr[1] == 0) ? arr[2 * b] : arr[b];
}

// ===========================================================================
// bf16x3-split NT GEMM on mma.sync (HMMA): C[m,n] = sum_k A[m,k]*B[n,k]
// A,B pre-split (hi,lo) bf16; fp32 accum in registers.
// 128x128 tile, BK=64, 3-stage cp.async pipeline, SW128-swizzled SMEM,
// ldmatrix TN fragments.
// mode 0: write fp32 C.  mode 1: bias-add then write split bf16 (Ch, Cl).
// ===========================================================================
#define GBM 128
#define GBN 128
#define GBK 64
#define NSTG 3
#define TILE_B (128 * 128)            // 16 KB: 128 rows x 128 B (64 bf16)
#define STAGE_B (4 * TILE_B)          // Ah, Al, Bh, Bl
#define SMEM_GEMM (128 + NSTG * STAGE_B)

__global__ __launch_bounds__(256, 1) void gemm_nt_mma(
    const __nv_bfloat16* __restrict__ Ah, const __nv_bfloat16* __restrict__ Al,
    int ldA, long long bsA,
    const __nv_bfloat16* __restrict__ Bh, const __nv_bfloat16* __restrict__ Bl,
    int ldB, long long bsB,
    int Kred,
    float* __restrict__ Cf, long long bsC, int ldC,
    __nv_bfloat16* __restrict__ Ch, __nv_bfloat16* __restrict__ Cl,
    const float* __restrict__ bias,
    int mode)
{
    extern __shared__ char smem_raw[];
    uint32_t sb0 = smem_u32(smem_raw);
    uint32_t sbase = (sb0 + 127u) & ~127u;
    char* stages = smem_raw + (sbase - sb0);

    const int tid = threadIdx.x;
    const int lane = tid & 31;
    const int wid = tid >> 5;
    const int wm = wid & 1;            // 2 m-subtiles of 64
    const int wn = wid >> 1;           // 4 n-subtiles of 32

    const int row0 = blockIdx.y * GBM;
    const int col0 = blockIdx.x * GBN;
    const long long bz = blockIdx.z;
    Ah += bz * bsA; Al += bz * bsA;
    Bh += bz * bsB; Bl += bz * bsB;

    float c[4][4][4];
#pragma unroll
    for (int mi = 0; mi < 4; mi++)
#pragma unroll
        for (int ni = 0; ni < 4; ni++)
#pragma unroll
            for (int q = 0; q < 4; q++) c[mi][ni][q] = 0.f;

    const int nch = Kred / GBK;

    // ---- copy-lane geometry: each thread copies 16B chunks ----
    const int rr = tid >> 3;           // 0..31 (row within 32-row slab)
    const int cc = tid & 7;            // 16B chunk within 128B row

    auto issue = [&](int ic) {
        char* st = stages + (ic % NSTG) * STAGE_B;
        const int k0 = ic * GBK;
#pragma unroll
        for (int p = 0; p < 4; p++) {
            const int row = rr + p * 32;
            const int sw = row * 128 + ((cc ^ (row & 7)) << 4);
            const uint32_t da = smem_u32(st + sw);
            const long long ka = (long long)(row0 + row) * ldA + k0 + cc * 8;
            const long long kb = (long long)(col0 + row) * ldB + k0 + cc * 8;
            CP16(da,                Ah + ka);
            CP16(da + TILE_B,       Al + ka);
            CP16(da + 2 * TILE_B,   Bh + kb);
            CP16(da + 3 * TILE_B,   Bl + kb);
        }
    };

    // ---- fragment-lane geometry (canonical TN ldmatrix patterns) ----
    const int a_r  = lane & 15;                       // A row within m16
    const int a_k2 = lane >> 4;                       // A 8-col half
    const int b_r  = ((lane >> 4) << 3) + (lane & 7); // B n-row within n16
    const int b_k2 = (lane >> 3) & 1;                 // B 8-col half

    auto compute = [&](int ic) {
        const uint32_t stu = smem_u32(stages + (ic % NSTG) * STAGE_B);
#pragma unroll
        for (int k16 = 0; k16 < GBK / 16; k16++) {
            uint32_t ah[4][4], al[4][4], bb[4][2];
            // A hi + lo fragments (warp rows wm*64 .. +64)
#pragma unroll
            for (int mi = 0; mi < 4; mi++) {
                const int row = wm * 64 + mi * 16 + a_r;
                const int kch = k16 * 2 + a_k2;
                const uint32_t off = row * 128 + ((kch ^ (row & 7)) << 4);
                LDSM_X4(ah[mi][0], ah[mi][1], ah[mi][2], ah[mi][3], stu + off);
                LDSM_X4(al[mi][0], al[mi][1], al[mi][2], al[mi][3],
                        stu + TILE_B + off);
            }
            // B hi fragments (warp cols wn*32 .. +32); x4 -> two n8 frags
#pragma unroll
            for (int pi = 0; pi < 2; pi++) {
                const int n = wn * 32 + pi * 16 + b_r;
                const int kch = k16 * 2 + b_k2;
                const uint32_t off = n * 128 + ((kch ^ (n & 7)) << 4);
                uint32_t t0, t1, t2, t3;
                LDSM_X4(t0, t1, t2, t3, stu + 2 * TILE_B + off);
                bb[2 * pi][0] = t0;     bb[2 * pi][1] = t1;
                bb[2 * pi + 1][0] = t2; bb[2 * pi + 1][1] = t3;
            }
            // hh
#pragma unroll
            for (int mi = 0; mi < 4; mi++)
#pragma unroll
                for (int ni = 0; ni < 4; ni++)
                    MMA16816(c[mi][ni], ah[mi], bb[ni][0], bb[ni][1]);
            // lh (Al x Bh)
#pragma unroll
            for (int mi = 0; mi < 4; mi++)
#pragma unroll
                for (int ni = 0; ni < 4; ni++)
                    MMA16816(c[mi][ni], al[mi], bb[ni][0], bb[ni][1]);
            // B lo overwrites bb
#pragma unroll
            for (int pi = 0; pi < 2; pi++) {
                const int n = wn * 32 + pi * 16 + b_r;
                const int kch = k16 * 2 + b_k2;
                const uint32_t off = n * 128 + ((kch ^ (n & 7)) << 4);
                uint32_t t0, t1, t2, t3;
                LDSM_X4(t0, t1, t2, t3, stu + 3 * TILE_B + off);
                bb[2 * pi][0] = t0;     bb[2 * pi][1] = t1;
                bb[2 * pi + 1][0] = t2; bb[2 * pi + 1][1] = t3;
            }
            // hl (Ah x Bl)
#pragma unroll
            for (int mi = 0; mi < 4; mi++)
#pragma unroll
                for (int ni = 0; ni < 4; ni++)
                    MMA16816(c[mi][ni], ah[mi], bb[ni][0], bb[ni][1]);
        }
    };

    // ---- pipeline ----
    issue(0); CP_COMMIT();
    issue(1); CP_COMMIT();
    for (int i = 0; i < nch; i++) {
        CP_WAIT1();
        __syncthreads();
        if (i + 2 < nch) issue(i + 2);
        CP_COMMIT();
        compute(i);
    }

    // ---- epilogue ----
    const int rr4 = lane >> 2;         // 0..7
    const int cc2 = (lane & 3) * 2;
    const int r_base = row0 + wm * 64;
    const int c_base = col0 + wn * 32;

    if (mode == 0) {
        float* out = Cf + bz * bsC;
#pragma unroll
        for (int mi = 0; mi < 4; mi++)
#pragma unroll
            for (int ni = 0; ni < 4; ni++) {
                const int r = r_base + mi * 16 + rr4;
                const int col = c_base + ni * 8 + cc2;
                *(float2*)(out + (long long)r * ldC + col) =
                    make_float2(c[mi][ni][0], c[mi][ni][1]);
                *(float2*)(out + (long long)(r + 8) * ldC + col) =
                    make_float2(c[mi][ni][2], c[mi][ni][3]);
            }
    } else {
#pragma unroll
        for (int mi = 0; mi < 4; mi++)
#pragma unroll
            for (int ni = 0; ni < 4; ni++) {
                const int r = r_base + mi * 16 + rr4;
                const int col = c_base + ni * 8 + cc2;
                const float bx = bias[col], by = bias[col + 1];
                float x0 = c[mi][ni][0] + bx, x1 = c[mi][ni][1] + by;
                float x2 = c[mi][ni][2] + bx, x3 = c[mi][ni][3] + by;
                __nv_bfloat16 h0, l0, h1, l1;
                split2(x0, h0, l0); split2(x1, h1, l1);
                *(uint32_t*)(Ch + (long long)r * ldC + col) = pack_bf(h0, h1);
                *(uint32_t*)(Cl + (long long)r * ldC + col) = pack_bf(l0, l1);
                split2(x2, h0, l0); split2(x3, h1, l1);
                *(uint32_t*)(Ch + (long long)(r + 8) * ldC + col) = pack_bf(h0, h1);
                *(uint32_t*)(Cl + (long long)(r + 8) * ldC + col) = pack_bf(l0, l1);
            }
    }
}

// ===========================================================================
// Elementwise split (fp32 -> hi/lo bf16) into strided dst (for concat buffers)
// ===========================================================================
__global__ void split_pad_kernel(const float* __restrict__ src, int R, int C,
                                 __nv_bfloat16* __restrict__ dh,
                                 __nv_bfloat16* __restrict__ dl,
                                 int ldD, int colOff)
{
    int idx = blockIdx.x * blockDim.x + threadIdx.x;
    int total = R * (C / 4);
    if (idx >= total) return;
    int r = idx / (C / 4);
    int c = (idx - r * (C / 4)) * 4;
    float4 v = *(const float4*)(src + (long long)r * C + c);
    __nv_bfloat16 h0, l0, h1, l1, h2, l2, h3, l3;
    split2(v.x, h0, l0); split2(v.y, h1, l1);
    split2(v.z, h2, l2); split2(v.w, h3, l3);
    long long base = (long long)r * ldD + colOff + c;
    *(uint2*)(dh + base) = make_uint2(pack_bf(h0, h1), pack_bf(h2, h3));
    *(uint2*)(dl + base) = make_uint2(pack_bf(l0, l1), pack_bf(l2, l3));
}

// ===========================================================================
// Transpose + split: src fp32 [R,C] (batched) -> dst hi/lo bf16 [C,R]
// ===========================================================================
__global__ void transpose_split_kernel(const float* __restrict__ src, long long bsS,
                                       int R, int C,
                                       __nv_bfloat16* __restrict__ dh,
                                       __nv_bfloat16* __restrict__ dl,
                                       long long bsD)
{
    __shared__ float tile[32][33];
    const long long b = blockIdx.z;
    src += b * bsS; dh += b * bsD; dl += b * bsD;
    const int c0 = blockIdx.x * 32;
    const int r0 = blockIdx.y * 32;
    const int x = threadIdx.x, y0 = threadIdx.y;
#pragma unroll
    for (int dy = 0; dy < 32; dy += 8) {
        tile[y0 + dy][x] = src[(long long)(r0 + y0 + dy) * C + c0 + x];
    }
    __syncthreads();
#pragma unroll
    for (int dy = 0; dy < 32; dy += 8) {
        int c = c0 + y0 + dy;
        float v = tile[x][y0 + dy];
        __nv_bfloat16 h, l;
        split2(v, h, l);
        dh[(long long)c * R + r0 + x] = h;
        dl[(long long)c * R + r0 + x] = l;
    }
}

// ===========================================================================
// Masked in-place row softmax + fused bf16 split of the weights.
// Mask: position (r,c) masked iff EXACTLY ONE of (r>=lenR[b]) / (c>=lenC[b]).
// ===========================================================================
__global__ __launch_bounds__(256) void softmax_mask_split_kernel(
    float* __restrict__ W, int Rdim, int Cdim,
    const int* __restrict__ lenR, const int* __restrict__ lenC,
    __nv_bfloat16* __restrict__ Wh, __nv_bfloat16* __restrict__ Wl)
{
    const int b = blockIdx.y;
    const int r = blockIdx.x;
    const long long rowoff = ((long long)b * Rdim + r) * (long long)Cdim;
    float* row = W + rowoff;
    const int lc = read_len(lenC, b);
    const bool rover = r >= read_len(lenR, b);
    const int tid = threadIdx.x;
    const int c0 = tid * 8;

    float vals[8];
    float4 v0 = *(float4*)(row + c0);
    float4 v1 = *(float4*)(row + c0 + 4);
    vals[0] = v0.x; vals[1] = v0.y; vals[2] = v0.z; vals[3] = v0.w;
    vals[4] = v1.x; vals[5] = v1.y; vals[6] = v1.z; vals[7] = v1.w;

    float m = -CUDART_INF_F;
#pragma unroll
    for (int i = 0; i < 8; i++) {
        bool cover = (c0 + i) >= lc;
        if (cover != rover) vals[i] = -CUDART_INF_F;   // XOR mask semantics
        m = fmaxf(m, vals[i]);
    }

    const int lane = tid & 31, wrp = tid >> 5;
    __shared__ float smax[8];
    __shared__ float ssum[8];
#pragma unroll
    for (int o = 16; o; o >>= 1) m = fmaxf(m, __shfl_xor_sync(0xffffffffu, m, o));
    if (!lane) smax[wrp] = m;
    __syncthreads();
    m = smax[0];
#pragma unroll
    for (int i = 1; i < 8; i++) m = fmaxf(m, smax[i]);

    float s = 0.f;
#pragma unroll
    for (int i = 0; i < 8; i++) {
        vals[i] = __expf(vals[i] - m);
        s += vals[i];
    }
#pragma unroll
    for (int o = 16; o; o >>= 1) s += __shfl_xor_sync(0xffffffffu, s, o);
    if (!lane) ssum[wrp] = s;
    __syncthreads();
    s = ssum[0];
#pragma unroll
    for (int i = 1; i < 8; i++) s += ssum[i];
    const float inv = 1.f / s;

    uint32_t hiw[4], low[4];
#pragma unroll
    for (int i = 0; i < 8; i++) vals[i] *= inv;
#pragma unroll
    for (int j = 0; j < 4; j++) {
        __nv_bfloat16 h0, l0, h1, l1;
        split2(vals[2 * j + 0], h0, l0);
        split2(vals[2 * j + 1], h1, l1);
        hiw[j] = pack_bf(h0, h1);
        low[j] = pack_bf(l0, l1);
    }

    v0.x = vals[0]; v0.y = vals[1]; v0.z = vals[2]; v0.w = vals[3];
    v1.x = vals[4]; v1.y = vals[5]; v1.z = vals[6]; v1.w = vals[7];
    *(float4*)(row + c0) = v0;
    *(float4*)(row + c0 + 4) = v1;
    *(uint4*)(Wh + rowoff + c0) = make_uint4(hiw[0], hiw[1], hiw[2], hiw[3]);
    *(uint4*)(Wl + rowoff + c0) = make_uint4(low[0], low[1], low[2], low[3]);
}

// ===========================================================================
// Launch
// ===========================================================================
extern "C" void kernel_launch(void* const* d_in, const int* in_sizes, int n_in,
                              void* d_out, int out_size)
{
    const float* k1   = (const float*)d_in[0];
    const float* k2   = (const float*)d_in[1];
    const float* pk1c = (const float*)d_in[2];
    const float* pk2c = (const float*)d_in[3];
    const float* v1   = (const float*)d_in[4];
    const float* v2   = (const float*)d_in[5];
    const float* W_k1  = (const float*)d_in[6];
    const float* b_k1  = (const float*)d_in[7];
    const float* W_k2  = (const float*)d_in[8];
    const float* b_k2  = (const float*)d_in[9];
    const float* W_pk1 = (const float*)d_in[10];
    const float* b_pk1 = (const float*)d_in[11];
    const float* W_pk2 = (const float*)d_in[12];
    const float* b_pk2 = (const float*)d_in[13];
    const int* l1 = (const int*)d_in[14];
    const int* l2 = (const int*)d_in[15];

    float* o1 = (float*)d_out;                               // [B,S2,DV]
    float* o2 = o1 + (long long)BB * SS * DV;                // [B,S1,DV]
    float* w1 = o2 + (long long)BB * SS * DV;                // [B,S2,S1]
    float* w2 = w1 + (long long)BB * SS * SS;                // [B,S1,S2]

    __nv_bfloat16 *cat1h, *cat1l, *cat2h, *cat2l;
    __nv_bfloat16 *k1ph, *k1pl, *k2ph, *k2pl, *pk1h, *pk1l, *pk2h, *pk2l;
    __nv_bfloat16 *wtk1h, *wtk1l, *wtk2h, *wtk2l, *wtpk1h, *wtpk1l, *wtpk2h, *wtpk2l;
    __nv_bfloat16 *vt1h, *vt1l, *vt2h, *vt2l;
    __nv_bfloat16 *w1h, *w1l, *w2h, *w2l;
    cudaGetSymbolAddress((void**)&cat1h, g_cat1_h); cudaGetSymbolAddress((void**)&cat1l, g_cat1_l);
    cudaGetSymbolAddress((void**)&cat2h, g_cat2_h); cudaGetSymbolAddress((void**)&cat2l, g_cat2_l);
    cudaGetSymbolAddress((void**)&k1ph, g_k1p_h);   cudaGetSymbolAddress((void**)&k1pl, g_k1p_l);
    cudaGetSymbolAddress((void**)&k2ph, g_k2p_h);   cudaGetSymbolAddress((void**)&k2pl, g_k2p_l);
    cudaGetSymbolAddress((void**)&pk1h, g_pk1_h);   cudaGetSymbolAddress((void**)&pk1l, g_pk1_l);
    cudaGetSymbolAddress((void**)&pk2h, g_pk2_h);   cudaGetSymbolAddress((void**)&pk2l, g_pk2_l);
    cudaGetSymbolAddress((void**)&wtk1h, g_wtk1_h); cudaGetSymbolAddress((void**)&wtk1l, g_wtk1_l);
    cudaGetSymbolAddress((void**)&wtk2h, g_wtk2_h); cudaGetSymbolAddress((void**)&wtk2l, g_wtk2_l);
    cudaGetSymbolAddress((void**)&wtpk1h, g_wtpk1_h); cudaGetSymbolAddress((void**)&wtpk1l, g_wtpk1_l);
    cudaGetSymbolAddress((void**)&wtpk2h, g_wtpk2_h); cudaGetSymbolAddress((void**)&wtpk2l, g_wtpk2_l);
    cudaGetSymbolAddress((void**)&vt1h, g_vt1_h);   cudaGetSymbolAddress((void**)&vt1l, g_vt1_l);
    cudaGetSymbolAddress((void**)&vt2h, g_vt2_h);   cudaGetSymbolAddress((void**)&vt2l, g_vt2_l);
    cudaGetSymbolAddress((void**)&w1h, g_w1_h);     cudaGetSymbolAddress((void**)&w1l, g_w1_l);
    cudaGetSymbolAddress((void**)&w2h, g_w2_h);     cudaGetSymbolAddress((void**)&w2l, g_w2_l);

    cudaFuncSetAttribute(gemm_nt_mma,
                         cudaFuncAttributeMaxDynamicSharedMemorySize, SMEM_GEMM);

    const int Mtot = BB * SS;   // 16384
    dim3 tb(32, 8);

    // 1) Weight transposes + splits (W [K,N] -> Wt [N,K])
    transpose_split_kernel<<<dim3(AD / 32, KD / 32, 1), tb>>>(W_k1, 0, KD, AD, wtk1h, wtk1l, 0);
    transpose_split_kernel<<<dim3(AD / 32, KD / 32, 1), tb>>>(W_k2, 0, KD, AD, wtk2h, wtk2l, 0);
    transpose_split_kernel<<<dim3(AD / 32, CATD / 32, 1), tb>>>(W_pk1, 0, CATD, AD, wtpk1h, wtpk1l, 0);
    transpose_split_kernel<<<dim3(AD / 32, CATD / 32, 1), tb>>>(W_pk2, 0, CATD, AD, wtpk2h, wtpk2l, 0);

    // 2) v transposes + splits: v [S,DV] -> vt [DV,S] per batch
    transpose_split_kernel<<<dim3(DV / 32, SS / 32, BB), tb>>>(
        v1, (long long)SS * DV, SS, DV, vt1h, vt1l, (long long)DV * SS);
    transpose_split_kernel<<<dim3(DV / 32, SS / 32, BB), tb>>>(
        v2, (long long)SS * DV, SS, DV, vt2h, vt2l, (long long)DV * SS);

    // 3) Input splits into concat buffers [Mtot, CATD]
    split_pad_kernel<<<(Mtot * (KD / 4) + 255) / 256, 256>>>(k1, Mtot, KD, cat1h, cat1l, CATD, 0);
    split_pad_kernel<<<(Mtot * (PKD / 4) + 255) / 256, 256>>>(pk1c, Mtot, PKD, cat1h, cat1l, CATD, KD);
    split_pad_kernel<<<(Mtot * (KD / 4) + 255) / 256, 256>>>(k2, Mtot, KD, cat2h, cat2l, CATD, 0);
    split_pad_kernel<<<(Mtot * (PKD / 4) + 255) / 256, 256>>>(pk2c, Mtot, PKD, cat2h, cat2l, CATD, KD);

    // 4) Projection GEMMs (mode 1: bias + split-bf16 out)
    gemm_nt_mma<<<dim3(AD / GBN, Mtot / GBM, 1), 256, SMEM_GEMM>>>(
        cat1h, cat1l, CATD, 0, wtk1h, wtk1l, KD, 0, KD,
        nullptr, 0, AD, k1ph, k1pl, b_k1, 1);
    gemm_nt_mma<<<dim3(AD / GBN, Mtot / GBM, 1), 256, SMEM_GEMM>>>(
        cat2h, cat2l, CATD, 0, wtk2h, wtk2l, KD, 0, KD,
        nullptr, 0, AD, k2ph, k2pl, b_k2, 1);
    gemm_nt_mma<<<dim3(AD / GBN, Mtot / GBM, 1), 256, SMEM_GEMM>>>(
        cat1h, cat1l, CATD, 0, wtpk1h, wtpk1l, CATD, 0, CATD,
        nullptr, 0, AD, pk1h, pk1l, b_pk1, 1);
    gemm_nt_mma<<<dim3(AD / GBN, Mtot / GBM, 1), 256, SMEM_GEMM>>>(
        cat2h, cat2l, CATD, 0, wtpk2h, wtpk2l, CATD, 0, CATD,
        nullptr, 0, AD, pk2h, pk2l, b_pk2, 1);

    // 5) Score GEMMs (mode 0, fp32 into w regions)
    //    w1_pre[t,s] = pk2[t,:].k1p[s,:]   w2_pre[s,t] = pk1[s,:].k2p[t,:]
    gemm_nt_mma<<<dim3(SS / GBN, SS / GBM, BB), 256, SMEM_GEMM>>>(
        pk2h, pk2l, AD, (long long)SS * AD, k1ph, k1pl, AD, (long long)SS * AD, AD,
        w1, (long long)SS * SS, SS, nullptr, nullptr, nullptr, 0);
    gemm_nt_mma<<<dim3(SS / GBN, SS / GBM, BB), 256, SMEM_GEMM>>>(
        pk1h, pk1l, AD, (long long)SS * AD, k2ph, k2pl, AD, (long long)SS * AD, AD,
        w2, (long long)SS * SS, SS, nullptr, nullptr, nullptr, 0);

    // 6) Masked softmax (in place) + fused bf16 split of weights
    softmax_mask_split_kernel<<<dim3(SS, BB), 256>>>(w1, SS, SS, l2, l1, w1h, w1l);
    softmax_mask_split_kernel<<<dim3(SS, BB), 256>>>(w2, SS, SS, l1, l2, w2h, w2l);

    // 7) Output GEMMs: o1 = w1 @ v1 (vt1 = v1^T), o2 = w2 @ v2
    gemm_nt_mma<<<dim3(DV / GBN, SS / GBM, BB), 256, SMEM_GEMM>>>(
        w1h, w1l, SS, (long long)SS * SS, vt1h, vt1l, SS, (long long)DV * SS, SS,
        o1, (long long)SS * DV, DV, nullptr, nullptr, nullptr, 0);
    gemm_nt_mma<<<dim3(DV / GBN, SS / GBM, BB), 256, SMEM_GEMM>>>(
        w2h, w2l, SS, (long long)SS * SS, vt2h, vt2l, SS, (long long)DV * SS, SS,
        o2, (long long)SS * DV, DV, nullptr, nullptr, nullptr, 0);
}

// round 8
// speedup vs baseline: 2.7816x; 1.1017x over previous
#include <cuda_runtime.h>
#include <cuda_bf16.h>
#include <math_constants.h>
#include <cstdint>

// Problem dims
#define BB 8
#define SS 2048      // S1 == S2
#define KD 512       // K1_DIM == K2_DIM
#define PKD 256
#define CATD 768     // KD + PKD
#define AD 512       // ATT_DIM
#define DV 512

// ===========================================================================
// bf16 split scratch (static __device__ — allocation-free). 16B aligned.
// ===========================================================================
__device__ __align__(16) __nv_bfloat16 g_cat1_h[BB * SS * CATD];
__device__ __align__(16) __nv_bfloat16 g_cat1_l[BB * SS * CATD];
__device__ __align__(16) __nv_bfloat16 g_cat2_h[BB * SS * CATD];
__device__ __align__(16) __nv_bfloat16 g_cat2_l[BB * SS * CATD];

__device__ __align__(16) __nv_bfloat16 g_k1p_h[BB * SS * AD];
__device__ __align__(16) __nv_bfloat16 g_k1p_l[BB * SS * AD];
__device__ __align__(16) __nv_bfloat16 g_k2p_h[BB * SS * AD];
__device__ __align__(16) __nv_bfloat16 g_k2p_l[BB * SS * AD];
__device__ __align__(16) __nv_bfloat16 g_pk1_h[BB * SS * AD];
__device__ __align__(16) __nv_bfloat16 g_pk1_l[BB * SS * AD];
__device__ __align__(16) __nv_bfloat16 g_pk2_h[BB * SS * AD];
__device__ __align__(16) __nv_bfloat16 g_pk2_l[BB * SS * AD];

__device__ __align__(16) __nv_bfloat16 g_wtk1_h[AD * KD];
__device__ __align__(16) __nv_bfloat16 g_wtk1_l[AD * KD];
__device__ __align__(16) __nv_bfloat16 g_wtk2_h[AD * KD];
__device__ __align__(16) __nv_bfloat16 g_wtk2_l[AD * KD];
__device__ __align__(16) __nv_bfloat16 g_wtpk1_h[AD * CATD];
__device__ __align__(16) __nv_bfloat16 g_wtpk1_l[AD * CATD];
__device__ __align__(16) __nv_bfloat16 g_wtpk2_h[AD * CATD];
__device__ __align__(16) __nv_bfloat16 g_wtpk2_l[AD * CATD];

__device__ __align__(16) __nv_bfloat16 g_vt1_h[BB * DV * SS];
__device__ __align__(16) __nv_bfloat16 g_vt1_l[BB * DV * SS];
__device__ __align__(16) __nv_bfloat16 g_vt2_h[BB * DV * SS];
__device__ __align__(16) __nv_bfloat16 g_vt2_l[BB * DV * SS];

__device__ __align__(16) __nv_bfloat16 g_w1_h[BB * SS * SS];
__device__ __align__(16) __nv_bfloat16 g_w1_l[BB * SS * SS];
__device__ __align__(16) __nv_bfloat16 g_w2_h[BB * SS * SS];
__device__ __align__(16) __nv_bfloat16 g_w2_l[BB * SS * SS];

// ===========================================================================
// Helpers
// ===========================================================================
__device__ __forceinline__ uint32_t smem_u32(const void* p) {
    uint32_t a;
    asm("{ .reg .u64 t; cvta.to.shared.u64 t, %1; cvt.u32.u64 %0, t; }"
        : "=r"(a) : "l"(p));
    return a;
}

#define CP16(dst, src) \
    asm volatile("cp.async.cg.shared.global [%0], [%1], 16;" :: "r"(dst), "l"(src))
#define CP_COMMIT() asm volatile("cp.async.commit_group;" ::: "memory")
#define CP_WAIT1()  asm volatile("cp.async.wait_group 1;" ::: "memory")

#define LDSM_X4(r0, r1, r2, r3, addr) \
    asm volatile("ldmatrix.sync.aligned.m8n8.x4.shared.b16 {%0,%1,%2,%3}, [%4];" \
                 : "=r"(r0), "=r"(r1), "=r"(r2), "=r"(r3) : "r"(addr))

#define MMA16816(c, a, b0, b1) \
    asm volatile("mma.sync.aligned.m16n8k16.row.col.f32.bf16.bf16.f32 " \
                 "{%0,%1,%2,%3}, {%4,%5,%6,%7}, {%8,%9}, {%0,%1,%2,%3};" \
                 : "+f"((c)[0]), "+f"((c)[1]), "+f"((c)[2]), "+f"((c)[3]) \
                 : "r"((a)[0]), "r"((a)[1]), "r"((a)[2]), "r"((a)[3]), \
                   "r"(b0), "r"(b1))

__device__ __forceinline__ void split2(float x, __nv_bfloat16& h, __nv_bfloat16& l) {
    h = __float2bfloat16(x);
    l = __float2bfloat16(x - __bfloat162float(h));
}
__device__ __forceinline__ uint32_t pack_bf(__nv_bfloat16 a, __nv_bfloat16 b) {
    return ((uint32_t)__bfloat16_as_ushort(b) << 16) | (uint32_t)__bfloat16_as_ushort(a);
}

// Dtype-robust length read (lengths in [S/2,S); int64 LE view has arr[1]==0)
__device__ __forceinline__ int read_len(const int* __restrict__ arr, int b) {
    return (arr[1] == 0) ? arr[2 * b] : arr[b];
}

// ===========================================================================
// bf16x3-split NT GEMM on mma.sync (HMMA): C[m,n] = sum_k A[m,k]*B[n,k]
// Two pointer-sets selected by blockIdx.z vs zsplit (merged launches).
// 128x128 tile, BK=64, 3-stage cp.async pipeline, SW128-swizzled SMEM.
// mode 0: write fp32 C.  mode 1: bias-add then write split bf16 (Ch, Cl).
// ===========================================================================
#define GBM 128
#define GBN 128
#define GBK 64
#define NSTG 3
#define TILE_B (128 * 128)            // 16 KB: 128 rows x 128 B (64 bf16)
#define STAGE_B (4 * TILE_B)          // Ah, Al, Bh, Bl
#define SMEM_GEMM (128 + NSTG * STAGE_B)

__global__ __launch_bounds__(256, 1) void gemm_nt_mma(
    const __nv_bfloat16* __restrict__ Ah0, const __nv_bfloat16* __restrict__ Al0,
    const __nv_bfloat16* __restrict__ Bh0, const __nv_bfloat16* __restrict__ Bl0,
    float* __restrict__ Cf0, __nv_bfloat16* __restrict__ Ch0,
    __nv_bfloat16* __restrict__ Cl0, const float* __restrict__ bias0,
    const __nv_bfloat16* __restrict__ Ah1, const __nv_bfloat16* __restrict__ Al1,
    const __nv_bfloat16* __restrict__ Bh1, const __nv_bfloat16* __restrict__ Bl1,
    float* __restrict__ Cf1, __nv_bfloat16* __restrict__ Ch1,
    __nv_bfloat16* __restrict__ Cl1, const float* __restrict__ bias1,
    int zsplit,
    int ldA, long long bsA, int ldB, long long bsB,
    int Kred, long long bsC, int ldC, int mode)
{
    extern __shared__ char smem_raw[];
    uint32_t sb0 = smem_u32(smem_raw);
    uint32_t sbase = (sb0 + 127u) & ~127u;
    char* stages = smem_raw + (sbase - sb0);

    const int tid = threadIdx.x;
    const int lane = tid & 31;
    const int wid = tid >> 5;
    const int wm = wid & 1;            // 2 m-subtiles of 64
    const int wn = wid >> 1;           // 4 n-subtiles of 32

    // ---- select pointer set by z ----
    const int zraw = blockIdx.z;
    const bool second = zraw >= zsplit;
    const long long bz = second ? (zraw - zsplit) : zraw;
    const __nv_bfloat16* Ah = second ? Ah1 : Ah0;
    const __nv_bfloat16* Al = second ? Al1 : Al0;
    const __nv_bfloat16* Bh = second ? Bh1 : Bh0;
    const __nv_bfloat16* Bl = second ? Bl1 : Bl0;
    float* Cf = second ? Cf1 : Cf0;
    __nv_bfloat16* Ch = second ? Ch1 : Ch0;
    __nv_bfloat16* Cl = second ? Cl1 : Cl0;
    const float* bias = second ? bias1 : bias0;

    const int row0 = blockIdx.y * GBM;
    const int col0 = blockIdx.x * GBN;
    Ah += bz * bsA; Al += bz * bsA;
    Bh += bz * bsB; Bl += bz * bsB;

    float c[4][4][4];
#pragma unroll
    for (int mi = 0; mi < 4; mi++)
#pragma unroll
        for (int ni = 0; ni < 4; ni++)
#pragma unroll
            for (int q = 0; q < 4; q++) c[mi][ni][q] = 0.f;

    const int nch = Kred / GBK;

    // ---- copy-lane geometry ----
    const int rr = tid >> 3;           // 0..31
    const int cc = tid & 7;            // 16B chunk within 128B row

    auto issue = [&](int ic) {
        char* st = stages + (ic % NSTG) * STAGE_B;
        const int k0 = ic * GBK;
#pragma unroll
        for (int p = 0; p < 4; p++) {
            const int row = rr + p * 32;
            const int sw = row * 128 + ((cc ^ (row & 7)) << 4);
            const uint32_t da = smem_u32(st + sw);
            const long long ka = (long long)(row0 + row) * ldA + k0 + cc * 8;
            const long long kb = (long long)(col0 + row) * ldB + k0 + cc * 8;
            CP16(da,                Ah + ka);
            CP16(da + TILE_B,       Al + ka);
            CP16(da + 2 * TILE_B,   Bh + kb);
            CP16(da + 3 * TILE_B,   Bl + kb);
        }
    };

    // ---- fragment-lane geometry ----
    const int a_r  = lane & 15;
    const int a_k2 = lane >> 4;
    const int b_r  = ((lane >> 4) << 3) + (lane & 7);
    const int b_k2 = (lane >> 3) & 1;

    auto compute = [&](int ic) {
        const uint32_t stu = smem_u32(stages + (ic % NSTG) * STAGE_B);
#pragma unroll
        for (int k16 = 0; k16 < GBK / 16; k16++) {
            uint32_t ah[4][4], al[4][4], bb[4][2];
#pragma unroll
            for (int mi = 0; mi < 4; mi++) {
                const int row = wm * 64 + mi * 16 + a_r;
                const int kch = k16 * 2 + a_k2;
                const uint32_t off = row * 128 + ((kch ^ (row & 7)) << 4);
                LDSM_X4(ah[mi][0], ah[mi][1], ah[mi][2], ah[mi][3], stu + off);
                LDSM_X4(al[mi][0], al[mi][1], al[mi][2], al[mi][3],
                        stu + TILE_B + off);
            }
#pragma unroll
            for (int pi = 0; pi < 2; pi++) {
                const int n = wn * 32 + pi * 16 + b_r;
                const int kch = k16 * 2 + b_k2;
                const uint32_t off = n * 128 + ((kch ^ (n & 7)) << 4);
                uint32_t t0, t1, t2, t3;
                LDSM_X4(t0, t1, t2, t3, stu + 2 * TILE_B + off);
                bb[2 * pi][0] = t0;     bb[2 * pi][1] = t1;
                bb[2 * pi + 1][0] = t2; bb[2 * pi + 1][1] = t3;
            }
#pragma unroll
            for (int mi = 0; mi < 4; mi++)
#pragma unroll
                for (int ni = 0; ni < 4; ni++)
                    MMA16816(c[mi][ni], ah[mi], bb[ni][0], bb[ni][1]);
#pragma unroll
            for (int mi = 0; mi < 4; mi++)
#pragma unroll
                for (int ni = 0; ni < 4; ni++)
                    MMA16816(c[mi][ni], al[mi], bb[ni][0], bb[ni][1]);
#pragma unroll
            for (int pi = 0; pi < 2; pi++) {
                const int n = wn * 32 + pi * 16 + b_r;
                const int kch = k16 * 2 + b_k2;
                const uint32_t off = n * 128 + ((kch ^ (n & 7)) << 4);
                uint32_t t0, t1, t2, t3;
                LDSM_X4(t0, t1, t2, t3, stu + 3 * TILE_B + off);
                bb[2 * pi][0] = t0;     bb[2 * pi][1] = t1;
                bb[2 * pi + 1][0] = t2; bb[2 * pi + 1][1] = t3;
            }
#pragma unroll
            for (int mi = 0; mi < 4; mi++)
#pragma unroll
                for (int ni = 0; ni < 4; ni++)
                    MMA16816(c[mi][ni], ah[mi], bb[ni][0], bb[ni][1]);
        }
    };

    // ---- pipeline ----
    issue(0); CP_COMMIT();
    issue(1); CP_COMMIT();
    for (int i = 0; i < nch; i++) {
        CP_WAIT1();
        __syncthreads();
        if (i + 2 < nch) issue(i + 2);
        CP_COMMIT();
        compute(i);
    }

    // ---- epilogue ----
    const int rr4 = lane >> 2;
    const int cc2 = (lane & 3) * 2;
    const int r_base = row0 + wm * 64;
    const int c_base = col0 + wn * 32;

    if (mode == 0) {
        float* out = Cf + bz * bsC;
#pragma unroll
        for (int mi = 0; mi < 4; mi++)
#pragma unroll
            for (int ni = 0; ni < 4; ni++) {
                const int r = r_base + mi * 16 + rr4;
                const int col = c_base + ni * 8 + cc2;
                *(float2*)(out + (long long)r * ldC + col) =
                    make_float2(c[mi][ni][0], c[mi][ni][1]);
                *(float2*)(out + (long long)(r + 8) * ldC + col) =
                    make_float2(c[mi][ni][2], c[mi][ni][3]);
            }
    } else {
#pragma unroll
        for (int mi = 0; mi < 4; mi++)
#pragma unroll
            for (int ni = 0; ni < 4; ni++) {
                const int r = r_base + mi * 16 + rr4;
                const int col = c_base + ni * 8 + cc2;
                const float bx = bias[col], by = bias[col + 1];
                float x0 = c[mi][ni][0] + bx, x1 = c[mi][ni][1] + by;
                float x2 = c[mi][ni][2] + bx, x3 = c[mi][ni][3] + by;
                __nv_bfloat16 h0, l0, h1, l1;
                split2(x0, h0, l0); split2(x1, h1, l1);
                *(uint32_t*)(Ch + (long long)r * ldC + col) = pack_bf(h0, h1);
                *(uint32_t*)(Cl + (long long)r * ldC + col) = pack_bf(l0, l1);
                split2(x2, h0, l0); split2(x3, h1, l1);
                *(uint32_t*)(Ch + (long long)(r + 8) * ldC + col) = pack_bf(h0, h1);
                *(uint32_t*)(Cl + (long long)(r + 8) * ldC + col) = pack_bf(l0, l1);
            }
    }
}

// ===========================================================================
// Fused concat split: both sides in one launch.
// side 0: [k1 | pk1c] -> cat1;  side 1: [k2 | pk2c] -> cat2
// ===========================================================================
__global__ void split_cat_kernel(const float* __restrict__ k1s,
                                 const float* __restrict__ pk1s,
                                 __nv_bfloat16* __restrict__ d1h,
                                 __nv_bfloat16* __restrict__ d1l,
                                 const float* __restrict__ k2s,
                                 const float* __restrict__ pk2s,
                                 __nv_bfloat16* __restrict__ d2h,
                                 __nv_bfloat16* __restrict__ d2l,
                                 int Mtot)
{
    const int chunks = CATD / 4;                    // 192 per row
    long long idx = (long long)blockIdx.x * blockDim.x + threadIdx.x;
    long long per_side = (long long)Mtot * chunks;
    if (idx >= 2 * per_side) return;
    const bool side2 = idx >= per_side;
    if (side2) idx -= per_side;
    const int r = (int)(idx / chunks);
    const int c = (int)(idx - (long long)r * chunks) * 4;

    const float* kk = side2 ? k2s : k1s;
    const float* pp = side2 ? pk2s : pk1s;
    __nv_bfloat16* dh = side2 ? d2h : d1h;
    __nv_bfloat16* dl = side2 ? d2l : d1l;

    float4 v;
    if (c < KD) v = *(const float4*)(kk + (long long)r * KD + c);
    else        v = *(const float4*)(pp + (long long)r * PKD + (c - KD));

    __nv_bfloat16 h0, l0, h1, l1, h2, l2, h3, l3;
    split2(v.x, h0, l0); split2(v.y, h1, l1);
    split2(v.z, h2, l2); split2(v.w, h3, l3);
    long long base = (long long)r * CATD + c;
    *(uint2*)(dh + base) = make_uint2(pack_bf(h0, h1), pack_bf(h2, h3));
    *(uint2*)(dl + base) = make_uint2(pack_bf(l0, l1), pack_bf(l2, l3));
}

// ===========================================================================
// Transpose + split with two pointer sets (merged launches):
// blockIdx.z < zsplit -> set 0 (batch z), else set 1 (batch z - zsplit).
// src fp32 [R,C] -> dst hi/lo bf16 [C,R]
// ===========================================================================
__global__ void transpose_split_kernel(
    const float* __restrict__ src0, __nv_bfloat16* __restrict__ dh0,
    __nv_bfloat16* __restrict__ dl0,
    const float* __restrict__ src1, __nv_bfloat16* __restrict__ dh1,
    __nv_bfloat16* __restrict__ dl1,
    int zsplit, long long bsS, int R, int C, long long bsD)
{
    __shared__ float tile[32][33];
    const int zraw = blockIdx.z;
    const bool second = zraw >= zsplit;
    const long long b = second ? (zraw - zsplit) : zraw;
    const float* src = (second ? src1 : src0) + b * bsS;
    __nv_bfloat16* dh = (second ? dh1 : dh0) + b * bsD;
    __nv_bfloat16* dl = (second ? dl1 : dl0) + b * bsD;

    const int c0 = blockIdx.x * 32;
    const int r0 = blockIdx.y * 32;
    const int x = threadIdx.x, y0 = threadIdx.y;
#pragma unroll
    for (int dy = 0; dy < 32; dy += 8) {
        tile[y0 + dy][x] = src[(long long)(r0 + y0 + dy) * C + c0 + x];
    }
    __syncthreads();
#pragma unroll
    for (int dy = 0; dy < 32; dy += 8) {
        int c = c0 + y0 + dy;
        float v = tile[x][y0 + dy];
        __nv_bfloat16 h, l;
        split2(v, h, l);
        dh[(long long)c * R + r0 + x] = h;
        dl[(long long)c * R + r0 + x] = l;
    }
}

// ===========================================================================
// Masked in-place row softmax + fused bf16 split; both w matrices in one
// launch: blockIdx.y in [0,2*BB): y < BB -> w1 (lenR=l2,lenC=l1), else w2.
// ===========================================================================
__global__ __launch_bounds__(256) void softmax_mask_split_kernel(
    float* __restrict__ W1, __nv_bfloat16* __restrict__ W1h,
    __nv_bfloat16* __restrict__ W1l,
    float* __restrict__ W2, __nv_bfloat16* __restrict__ W2h,
    __nv_bfloat16* __restrict__ W2l,
    const int* __restrict__ l1, const int* __restrict__ l2)
{
    const int yraw = blockIdx.y;
    const bool second = yraw >= BB;
    const int b = second ? (yraw - BB) : yraw;
    float* W = second ? W2 : W1;
    __nv_bfloat16* Wh = second ? W2h : W1h;
    __nv_bfloat16* Wl = second ? W2l : W1l;
    const int* lenR = second ? l1 : l2;
    const int* lenC = second ? l2 : l1;

    const int r = blockIdx.x;
    const long long rowoff = ((long long)b * SS + r) * (long long)SS;
    float* row = W + rowoff;
    const int lc = read_len(lenC, b);
    const bool rover = r >= read_len(lenR, b);
    const int tid = threadIdx.x;
    const int c0 = tid * 8;

    float vals[8];
    float4 v0 = *(float4*)(row + c0);
    float4 v1 = *(float4*)(row + c0 + 4);
    vals[0] = v0.x; vals[1] = v0.y; vals[2] = v0.z; vals[3] = v0.w;
    vals[4] = v1.x; vals[5] = v1.y; vals[6] = v1.z; vals[7] = v1.w;

    float m = -CUDART_INF_F;
#pragma unroll
    for (int i = 0; i < 8; i++) {
        bool cover = (c0 + i) >= lc;
        if (cover != rover) vals[i] = -CUDART_INF_F;   // XOR mask semantics
        m = fmaxf(m, vals[i]);
    }

    const int lane = tid & 31, wrp = tid >> 5;
    __shared__ float smax[8];
    __shared__ float ssum[8];
#pragma unroll
    for (int o = 16; o; o >>= 1) m = fmaxf(m, __shfl_xor_sync(0xffffffffu, m, o));
    if (!lane) smax[wrp] = m;
    __syncthreads();
    m = smax[0];
#pragma unroll
    for (int i = 1; i < 8; i++) m = fmaxf(m, smax[i]);

    float s = 0.f;
#pragma unroll
    for (int i = 0; i < 8; i++) {
        vals[i] = __expf(vals[i] - m);
        s += vals[i];
    }
#pragma unroll
    for (int o = 16; o; o >>= 1) s += __shfl_xor_sync(0xffffffffu, s, o);
    if (!lane) ssum[wrp] = s;
    __syncthreads();
    s = ssum[0];
#pragma unroll
    for (int i = 1; i < 8; i++) s += ssum[i];
    const float inv = 1.f / s;

    uint32_t hiw[4], low[4];
#pragma unroll
    for (int i = 0; i < 8; i++) vals[i] *= inv;
#pragma unroll
    for (int j = 0; j < 4; j++) {
        __nv_bfloat16 h0, l0, h1, l1;
        split2(vals[2 * j + 0], h0, l0);
        split2(vals[2 * j + 1], h1, l1);
        hiw[j] = pack_bf(h0, h1);
        low[j] = pack_bf(l0, l1);
    }

    v0.x = vals[0]; v0.y = vals[1]; v0.z = vals[2]; v0.w = vals[3];
    v1.x = vals[4]; v1.y = vals[5]; v1.z = vals[6]; v1.w = vals[7];
    *(float4*)(row + c0) = v0;
    *(float4*)(row + c0 + 4) = v1;
    *(uint4*)(Wh + rowoff + c0) = make_uint4(hiw[0], hiw[1], hiw[2], hiw[3]);
    *(uint4*)(Wl + rowoff + c0) = make_uint4(low[0], low[1], low[2], low[3]);
}

// ===========================================================================
// Launch
// ===========================================================================
extern "C" void kernel_launch(void* const* d_in, const int* in_sizes, int n_in,
                              void* d_out, int out_size)
{
    const float* k1   = (const float*)d_in[0];
    const float* k2   = (const float*)d_in[1];
    const float* pk1c = (const float*)d_in[2];
    const float* pk2c = (const float*)d_in[3];
    const float* v1   = (const float*)d_in[4];
    const float* v2   = (const float*)d_in[5];
    const float* W_k1  = (const float*)d_in[6];
    const float* b_k1  = (const float*)d_in[7];
    const float* W_k2  = (const float*)d_in[8];
    const float* b_k2  = (const float*)d_in[9];
    const float* W_pk1 = (const float*)d_in[10];
    const float* b_pk1 = (const float*)d_in[11];
    const float* W_pk2 = (const float*)d_in[12];
    const float* b_pk2 = (const float*)d_in[13];
    const int* l1 = (const int*)d_in[14];
    const int* l2 = (const int*)d_in[15];

    float* o1 = (float*)d_out;                               // [B,S2,DV]
    float* o2 = o1 + (long long)BB * SS * DV;                // [B,S1,DV]
    float* w1 = o2 + (long long)BB * SS * DV;                // [B,S2,S1]
    float* w2 = w1 + (long long)BB * SS * SS;                // [B,S1,S2]

    __nv_bfloat16 *cat1h, *cat1l, *cat2h, *cat2l;
    __nv_bfloat16 *k1ph, *k1pl, *k2ph, *k2pl, *pk1h, *pk1l, *pk2h, *pk2l;
    __nv_bfloat16 *wtk1h, *wtk1l, *wtk2h, *wtk2l, *wtpk1h, *wtpk1l, *wtpk2h, *wtpk2l;
    __nv_bfloat16 *vt1h, *vt1l, *vt2h, *vt2l;
    __nv_bfloat16 *w1h, *w1l, *w2h, *w2l;
    cudaGetSymbolAddress((void**)&cat1h, g_cat1_h); cudaGetSymbolAddress((void**)&cat1l, g_cat1_l);
    cudaGetSymbolAddress((void**)&cat2h, g_cat2_h); cudaGetSymbolAddress((void**)&cat2l, g_cat2_l);
    cudaGetSymbolAddress((void**)&k1ph, g_k1p_h);   cudaGetSymbolAddress((void**)&k1pl, g_k1p_l);
    cudaGetSymbolAddress((void**)&k2ph, g_k2p_h);   cudaGetSymbolAddress((void**)&k2pl, g_k2p_l);
    cudaGetSymbolAddress((void**)&pk1h, g_pk1_h);   cudaGetSymbolAddress((void**)&pk1l, g_pk1_l);
    cudaGetSymbolAddress((void**)&pk2h, g_pk2_h);   cudaGetSymbolAddress((void**)&pk2l, g_pk2_l);
    cudaGetSymbolAddress((void**)&wtk1h, g_wtk1_h); cudaGetSymbolAddress((void**)&wtk1l, g_wtk1_l);
    cudaGetSymbolAddress((void**)&wtk2h, g_wtk2_h); cudaGetSymbolAddress((void**)&wtk2l, g_wtk2_l);
    cudaGetSymbolAddress((void**)&wtpk1h, g_wtpk1_h); cudaGetSymbolAddress((void**)&wtpk1l, g_wtpk1_l);
    cudaGetSymbolAddress((void**)&wtpk2h, g_wtpk2_h); cudaGetSymbolAddress((void**)&wtpk2l, g_wtpk2_l);
    cudaGetSymbolAddress((void**)&vt1h, g_vt1_h);   cudaGetSymbolAddress((void**)&vt1l, g_vt1_l);
    cudaGetSymbolAddress((void**)&vt2h, g_vt2_h);   cudaGetSymbolAddress((void**)&vt2l, g_vt2_l);
    cudaGetSymbolAddress((void**)&w1h, g_w1_h);     cudaGetSymbolAddress((void**)&w1l, g_w1_l);
    cudaGetSymbolAddress((void**)&w2h, g_w2_h);     cudaGetSymbolAddress((void**)&w2l, g_w2_l);

    cudaFuncSetAttribute(gemm_nt_mma,
                         cudaFuncAttributeMaxDynamicSharedMemorySize, SMEM_GEMM);

    const int Mtot = BB * SS;   // 16384
    dim3 tb(32, 8);

    // (0) k-weight transposes merged (z=2)
    transpose_split_kernel<<<dim3(AD / 32, KD / 32, 2), tb>>>(
        W_k1, wtk1h, wtk1l, W_k2, wtk2h, wtk2l, 1, 0, KD, AD, 0);
    // (1) pk-weight transposes merged (z=2)
    transpose_split_kernel<<<dim3(AD / 32, CATD / 32, 2), tb>>>(
        W_pk1, wtpk1h, wtpk1l, W_pk2, wtpk2h, wtpk2l, 1, 0, CATD, AD, 0);
    // (2) v transposes merged (z=16)
    transpose_split_kernel<<<dim3(DV / 32, SS / 32, 2 * BB), tb>>>(
        v1, vt1h, vt1l, v2, vt2h, vt2l, BB,
        (long long)SS * DV, SS, DV, (long long)DV * SS);
    // (3) input concat splits, both sides in one launch
    {
        long long total = 2LL * Mtot * (CATD / 4);
        split_cat_kernel<<<(int)((total + 255) / 256), 256>>>(
            k1, pk1c, cat1h, cat1l, k2, pk2c, cat2h, cat2l, Mtot);
    }

    // (4) k-projection GEMMs merged (z=2): k1p, k2p
    gemm_nt_mma<<<dim3(AD / GBN, Mtot / GBM, 2), 256, SMEM_GEMM>>>(
        cat1h, cat1l, wtk1h, wtk1l, nullptr, k1ph, k1pl, b_k1,
        cat2h, cat2l, wtk2h, wtk2l, nullptr, k2ph, k2pl, b_k2,
        1, CATD, 0, KD, 0, KD, 0, AD, 1);
    // (5) pk-projection GEMMs merged (z=2): pk1, pk2   <- ncu -s 5 target
    gemm_nt_mma<<<dim3(AD / GBN, Mtot / GBM, 2), 256, SMEM_GEMM>>>(
        cat1h, cat1l, wtpk1h, wtpk1l, nullptr, pk1h, pk1l, b_pk1,
        cat2h, cat2l, wtpk2h, wtpk2l, nullptr, pk2h, pk2l, b_pk2,
        1, CATD, 0, CATD, 0, CATD, 0, AD, 1);

    // (6) score GEMMs merged (z=16, fp32 into w regions)
    //     w1_pre[t,s] = pk2[t,:].k1p[s,:]   w2_pre[s,t] = pk1[s,:].k2p[t,:]
    gemm_nt_mma<<<dim3(SS / GBN, SS / GBM, 2 * BB), 256, SMEM_GEMM>>>(
        pk2h, pk2l, k1ph, k1pl, w1, nullptr, nullptr, nullptr,
        pk1h, pk1l, k2ph, k2pl, w2, nullptr, nullptr, nullptr,
        BB, AD, (long long)SS * AD, AD, (long long)SS * AD,
        AD, (long long)SS * SS, SS, 0);

    // (7) masked softmax + split, both w matrices (grid.y = 16)
    softmax_mask_split_kernel<<<dim3(SS, 2 * BB), 256>>>(
        w1, w1h, w1l, w2, w2h, w2l, l1, l2);

    // (8) output GEMMs merged (z=16): o1 = w1 @ v1, o2 = w2 @ v2
    gemm_nt_mma<<<dim3(DV / GBN, SS / GBM, 2 * BB), 256, SMEM_GEMM>>>(
        w1h, w1l, vt1h, vt1l, o1, nullptr, nullptr, nullptr,
        w2h, w2l, vt2h, vt2l, o2, nullptr, nullptr, nullptr,
        BB, SS, (long long)SS * SS, SS, (long long)DV * SS,
        SS, (long long)SS * DV, DV, 0);
}

// round 10
// speedup vs baseline: 2.7932x; 1.0042x over previous
#include <cuda_runtime.h>
#include <cuda_bf16.h>
#include <math_constants.h>
#include <cstdint>

// Problem dims
#define BB 8
#define SS 2048      // S1 == S2
#define KD 512       // K1_DIM == K2_DIM
#define PKD 256
#define CATD 768     // KD + PKD
#define AD 512       // ATT_DIM
#define DV 512

// ===========================================================================
// bf16 split scratch (static __device__ — allocation-free). 16B aligned.
// ===========================================================================
__device__ __align__(16) __nv_bfloat16 g_cat1_h[BB * SS * CATD];
__device__ __align__(16) __nv_bfloat16 g_cat1_l[BB * SS * CATD];
__device__ __align__(16) __nv_bfloat16 g_cat2_h[BB * SS * CATD];
__device__ __align__(16) __nv_bfloat16 g_cat2_l[BB * SS * CATD];

__device__ __align__(16) __nv_bfloat16 g_k1p_h[BB * SS * AD];
__device__ __align__(16) __nv_bfloat16 g_k1p_l[BB * SS * AD];
__device__ __align__(16) __nv_bfloat16 g_k2p_h[BB * SS * AD];
__device__ __align__(16) __nv_bfloat16 g_k2p_l[BB * SS * AD];
__device__ __align__(16) __nv_bfloat16 g_pk1_h[BB * SS * AD];
__device__ __align__(16) __nv_bfloat16 g_pk1_l[BB * SS * AD];
__device__ __align__(16) __nv_bfloat16 g_pk2_h[BB * SS * AD];
__device__ __align__(16) __nv_bfloat16 g_pk2_l[BB * SS * AD];

__device__ __align__(16) __nv_bfloat16 g_wtk1_h[AD * KD];
__device__ __align__(16) __nv_bfloat16 g_wtk1_l[AD * KD];
__device__ __align__(16) __nv_bfloat16 g_wtk2_h[AD * KD];
__device__ __align__(16) __nv_bfloat16 g_wtk2_l[AD * KD];
__device__ __align__(16) __nv_bfloat16 g_wtpk1_h[AD * CATD];
__device__ __align__(16) __nv_bfloat16 g_wtpk1_l[AD * CATD];
__device__ __align__(16) __nv_bfloat16 g_wtpk2_h[AD * CATD];
__device__ __align__(16) __nv_bfloat16 g_wtpk2_l[AD * CATD];

__device__ __align__(16) __nv_bfloat16 g_vt1_h[BB * DV * SS];
__device__ __align__(16) __nv_bfloat16 g_vt1_l[BB * DV * SS];
__device__ __align__(16) __nv_bfloat16 g_vt2_h[BB * DV * SS];
__device__ __align__(16) __nv_bfloat16 g_vt2_l[BB * DV * SS];

__device__ __align__(16) __nv_bfloat16 g_w1_h[BB * SS * SS];
__device__ __align__(16) __nv_bfloat16 g_w1_l[BB * SS * SS];
__device__ __align__(16) __nv_bfloat16 g_w2_h[BB * SS * SS];
__device__ __align__(16) __nv_bfloat16 g_w2_l[BB * SS * SS];

// ===========================================================================
// Helpers
// ===========================================================================
__device__ __forceinline__ uint32_t smem_u32(const void* p) {
    uint32_t a;
    asm("{ .reg .u64 t; cvta.to.shared.u64 t, %1; cvt.u32.u64 %0, t; }"
        : "=r"(a) : "l"(p));
    return a;
}

#define CP16(dst, src) \
    asm volatile("cp.async.cg.shared.global [%0], [%1], 16;" :: "r"(dst), "l"(src))
#define CP_COMMIT() asm volatile("cp.async.commit_group;" ::: "memory")
#define CP_WAIT1()  asm volatile("cp.async.wait_group 1;" ::: "memory")

#define LDSM_X4(r0, r1, r2, r3, addr) \
    asm volatile("ldmatrix.sync.aligned.m8n8.x4.shared.b16 {%0,%1,%2,%3}, [%4];" \
                 : "=r"(r0), "=r"(r1), "=r"(r2), "=r"(r3) : "r"(addr))

#define MMA16816(c, a, b0, b1) \
    asm volatile("mma.sync.aligned.m16n8k16.row.col.f32.bf16.bf16.f32 " \
                 "{%0,%1,%2,%3}, {%4,%5,%6,%7}, {%8,%9}, {%0,%1,%2,%3};" \
                 : "+f"((c)[0]), "+f"((c)[1]), "+f"((c)[2]), "+f"((c)[3]) \
                 : "r"((a)[0]), "r"((a)[1]), "r"((a)[2]), "r"((a)[3]), \
                   "r"(b0), "r"(b1))

__device__ __forceinline__ void split2(float x, __nv_bfloat16& h, __nv_bfloat16& l) {
    h = __float2bfloat16(x);
    l = __float2bfloat16(x - __bfloat162float(h));
}
__device__ __forceinline__ uint32_t pack_bf(__nv_bfloat16 a, __nv_bfloat16 b) {
    return ((uint32_t)__bfloat16_as_ushort(b) << 16) | (uint32_t)__bfloat16_as_ushort(a);
}

// Dtype-robust length read (lengths in [S/2,S); int64 LE view has arr[1]==0)
__device__ __forceinline__ int read_len(const int* __restrict__ arr, int b) {
    return (arr[1] == 0) ? arr[2 * b] : arr[b];
}

// ===========================================================================
// bf16x3-split NT GEMM on mma.sync (HMMA): C[m,n] = sum_k A[m,k]*B[n,k]
// Two pointer-sets selected by blockIdx.z vs zsplit (merged launches).
// 128x128 tile, BK=64, 3-stage cp.async pipeline, SW128-swizzled SMEM.
// mode 0: write fp32 C.  mode 1: bias-add then write split bf16 (Ch, Cl).
// (UNCHANGED from R8 — proven core.)
// ===========================================================================
#define GBM 128
#define GBN 128
#define GBK 64
#define NSTG 3
#define TILE_B (128 * 128)            // 16 KB: 128 rows x 128 B (64 bf16)
#define STAGE_B (4 * TILE_B)          // Ah, Al, Bh, Bl
#define SMEM_GEMM (128 + NSTG * STAGE_B)

__global__ __launch_bounds__(256, 1) void gemm_nt_mma(
    const __nv_bfloat16* __restrict__ Ah0, const __nv_bfloat16* __restrict__ Al0,
    const __nv_bfloat16* __restrict__ Bh0, const __nv_bfloat16* __restrict__ Bl0,
    float* __restrict__ Cf0, __nv_bfloat16* __restrict__ Ch0,
    __nv_bfloat16* __restrict__ Cl0, const float* __restrict__ bias0,
    const __nv_bfloat16* __restrict__ Ah1, const __nv_bfloat16* __restrict__ Al1,
    const __nv_bfloat16* __restrict__ Bh1, const __nv_bfloat16* __restrict__ Bl1,
    float* __restrict__ Cf1, __nv_bfloat16* __restrict__ Ch1,
    __nv_bfloat16* __restrict__ Cl1, const float* __restrict__ bias1,
    int zsplit,
    int ldA, long long bsA, int ldB, long long bsB,
    int Kred, long long bsC, int ldC, int mode)
{
    extern __shared__ char smem_raw[];
    uint32_t sb0 = smem_u32(smem_raw);
    uint32_t sbase = (sb0 + 127u) & ~127u;
    char* stages = smem_raw + (sbase - sb0);

    const int tid = threadIdx.x;
    const int lane = tid & 31;
    const int wid = tid >> 5;
    const int wm = wid & 1;            // 2 m-subtiles of 64
    const int wn = wid >> 1;           // 4 n-subtiles of 32

    const int zraw = blockIdx.z;
    const bool second = zraw >= zsplit;
    const long long bz = second ? (zraw - zsplit) : zraw;
    const __nv_bfloat16* Ah = second ? Ah1 : Ah0;
    const __nv_bfloat16* Al = second ? Al1 : Al0;
    const __nv_bfloat16* Bh = second ? Bh1 : Bh0;
    const __nv_bfloat16* Bl = second ? Bl1 : Bl0;
    float* Cf = second ? Cf1 : Cf0;
    __nv_bfloat16* Ch = second ? Ch1 : Ch0;
    __nv_bfloat16* Cl = second ? Cl1 : Cl0;
    const float* bias = second ? bias1 : bias0;

    const int row0 = blockIdx.y * GBM;
    const int col0 = blockIdx.x * GBN;
    Ah += bz * bsA; Al += bz * bsA;
    Bh += bz * bsB; Bl += bz * bsB;

    float c[4][4][4];
#pragma unroll
    for (int mi = 0; mi < 4; mi++)
#pragma unroll
        for (int ni = 0; ni < 4; ni++)
#pragma unroll
            for (int q = 0; q < 4; q++) c[mi][ni][q] = 0.f;

    const int nch = Kred / GBK;

    const int rr = tid >> 3;           // 0..31
    const int cc = tid & 7;            // 16B chunk within 128B row

    auto issue = [&](int ic) {
        char* st = stages + (ic % NSTG) * STAGE_B;
        const int k0 = ic * GBK;
#pragma unroll
        for (int p = 0; p < 4; p++) {
            const int row = rr + p * 32;
            const int sw = row * 128 + ((cc ^ (row & 7)) << 4);
            const uint32_t da = smem_u32(st + sw);
            const long long ka = (long long)(row0 + row) * ldA + k0 + cc * 8;
            const long long kb = (long long)(col0 + row) * ldB + k0 + cc * 8;
            CP16(da,                Ah + ka);
            CP16(da + TILE_B,       Al + ka);
            CP16(da + 2 * TILE_B,   Bh + kb);
            CP16(da + 3 * TILE_B,   Bl + kb);
        }
    };

    const int a_r  = lane & 15;
    const int a_k2 = lane >> 4;
    const int b_r  = ((lane >> 4) << 3) + (lane & 7);
    const int b_k2 = (lane >> 3) & 1;

    auto compute = [&](int ic) {
        const uint32_t stu = smem_u32(stages + (ic % NSTG) * STAGE_B);
#pragma unroll
        for (int k16 = 0; k16 < GBK / 16; k16++) {
            uint32_t ah[4][4], al[4][4], bb[4][2];
#pragma unroll
            for (int mi = 0; mi < 4; mi++) {
                const int row = wm * 64 + mi * 16 + a_r;
                const int kch = k16 * 2 + a_k2;
                const uint32_t off = row * 128 + ((kch ^ (row & 7)) << 4);
                LDSM_X4(ah[mi][0], ah[mi][1], ah[mi][2], ah[mi][3], stu + off);
                LDSM_X4(al[mi][0], al[mi][1], al[mi][2], al[mi][3],
                        stu + TILE_B + off);
            }
#pragma unroll
            for (int pi = 0; pi < 2; pi++) {
                const int n = wn * 32 + pi * 16 + b_r;
                const int kch = k16 * 2 + b_k2;
                const uint32_t off = n * 128 + ((kch ^ (n & 7)) << 4);
                uint32_t t0, t1, t2, t3;
                LDSM_X4(t0, t1, t2, t3, stu + 2 * TILE_B + off);
                bb[2 * pi][0] = t0;     bb[2 * pi][1] = t1;
                bb[2 * pi + 1][0] = t2; bb[2 * pi + 1][1] = t3;
            }
#pragma unroll
            for (int mi = 0; mi < 4; mi++)
#pragma unroll
                for (int ni = 0; ni < 4; ni++)
                    MMA16816(c[mi][ni], ah[mi], bb[ni][0], bb[ni][1]);
#pragma unroll
            for (int mi = 0; mi < 4; mi++)
#pragma unroll
                for (int ni = 0; ni < 4; ni++)
                    MMA16816(c[mi][ni], al[mi], bb[ni][0], bb[ni][1]);
#pragma unroll
            for (int pi = 0; pi < 2; pi++) {
                const int n = wn * 32 + pi * 16 + b_r;
                const int kch = k16 * 2 + b_k2;
                const uint32_t off = n * 128 + ((kch ^ (n & 7)) << 4);
                uint32_t t0, t1, t2, t3;
                LDSM_X4(t0, t1, t2, t3, stu + 3 * TILE_B + off);
                bb[2 * pi][0] = t0;     bb[2 * pi][1] = t1;
                bb[2 * pi + 1][0] = t2; bb[2 * pi + 1][1] = t3;
            }
#pragma unroll
            for (int mi = 0; mi < 4; mi++)
#pragma unroll
                for (int ni = 0; ni < 4; ni++)
                    MMA16816(c[mi][ni], ah[mi], bb[ni][0], bb[ni][1]);
        }
    };

    issue(0); CP_COMMIT();
    issue(1); CP_COMMIT();
    for (int i = 0; i < nch; i++) {
        CP_WAIT1();
        __syncthreads();
        if (i + 2 < nch) issue(i + 2);
        CP_COMMIT();
        compute(i);
    }

    const int rr4 = lane >> 2;
    const int cc2 = (lane & 3) * 2;
    const int r_base = row0 + wm * 64;
    const int c_base = col0 + wn * 32;

    if (mode == 0) {
        float* out = Cf + bz * bsC;
#pragma unroll
        for (int mi = 0; mi < 4; mi++)
#pragma unroll
            for (int ni = 0; ni < 4; ni++) {
                const int r = r_base + mi * 16 + rr4;
                const int col = c_base + ni * 8 + cc2;
                *(float2*)(out + (long long)r * ldC + col) =
                    make_float2(c[mi][ni][0], c[mi][ni][1]);
                *(float2*)(out + (long long)(r + 8) * ldC + col) =
                    make_float2(c[mi][ni][2], c[mi][ni][3]);
            }
    } else {
#pragma unroll
        for (int mi = 0; mi < 4; mi++)
#pragma unroll
            for (int ni = 0; ni < 4; ni++) {
                const int r = r_base + mi * 16 + rr4;
                const int col = c_base + ni * 8 + cc2;
                const float bx = bias[col], by = bias[col + 1];
                float x0 = c[mi][ni][0] + bx, x1 = c[mi][ni][1] + by;
                float x2 = c[mi][ni][2] + bx, x3 = c[mi][ni][3] + by;
                __nv_bfloat16 h0, l0, h1, l1;
                split2(x0, h0, l0); split2(x1, h1, l1);
                *(uint32_t*)(Ch + (long long)r * ldC + col) = pack_bf(h0, h1);
                *(uint32_t*)(Cl + (long long)r * ldC + col) = pack_bf(l0, l1);
                split2(x2, h0, l0); split2(x3, h1, l1);
                *(uint32_t*)(Ch + (long long)(r + 8) * ldC + col) = pack_bf(h0, h1);
                *(uint32_t*)(Cl + (long long)(r + 8) * ldC + col) = pack_bf(l0, l1);
            }
    }
}

// ===========================================================================
// ONE fused prep kernel: all transposes + concat splits, block-range dispatch.
// Segments (256-thread blocks):
//   [0, 512):            k-weight transposes  (2 sides x 16x16 tiles)
//   [512, 1280):         pk-weight transposes (2 sides x 24x16 tiles)
//   [1280, 17664):       v transposes         (16 batches x 64x16 tiles)
//   [17664, 42240):      concat splits        (24576 blocks x 256 chunks)
// ===========================================================================
#define NB_WTK   512
#define NB_WTPK  768
#define NB_VT    16384
#define NB_CAT   24576
#define NB_PREP  (NB_WTK + NB_WTPK + NB_VT + NB_CAT)

__device__ __forceinline__ void transpose_tile(
    float (*tile)[33],
    const float* __restrict__ src, __nv_bfloat16* __restrict__ dh,
    __nv_bfloat16* __restrict__ dl, int R, int C, int tr, int tc)
{
    const int x = threadIdx.x & 31;
    const int y0 = threadIdx.x >> 5;       // 0..7
    const int r0 = tr * 32, c0 = tc * 32;
#pragma unroll
    for (int dy = 0; dy < 32; dy += 8)
        tile[y0 + dy][x] = src[(long long)(r0 + y0 + dy) * C + c0 + x];
    __syncthreads();
#pragma unroll
    for (int dy = 0; dy < 32; dy += 8) {
        const int c = c0 + y0 + dy;
        float v = tile[x][y0 + dy];
        __nv_bfloat16 h, l;
        split2(v, h, l);
        dh[(long long)c * R + r0 + x] = h;
        dl[(long long)c * R + r0 + x] = l;
    }
}

__global__ __launch_bounds__(256) void prep_kernel(
    const float* __restrict__ k1,  const float* __restrict__ pk1c,
    const float* __restrict__ k2,  const float* __restrict__ pk2c,
    const float* __restrict__ v1,  const float* __restrict__ v2,
    const float* __restrict__ W_k1, const float* __restrict__ W_k2,
    const float* __restrict__ W_pk1, const float* __restrict__ W_pk2)
{
    __shared__ float tile[32][33];
    const int b = blockIdx.x;
    const int tid = threadIdx.x;

    if (b < NB_WTK) {
        // W_k transposes: src [KD, AD] -> [AD, KD]; 256 tiles per side
        const int side = b >> 8;
        const int rem = b & 255;
        const int tr = rem >> 4, tc = rem & 15;
        transpose_tile(tile,
                       side ? W_k2 : W_k1,
                       side ? g_wtk2_h : g_wtk1_h,
                       side ? g_wtk2_l : g_wtk1_l,
                       KD, AD, tr, tc);
        return;
    }
    if (b < NB_WTK + NB_WTPK) {
        // W_pk transposes: src [CATD, AD] -> [AD, CATD]; 384 tiles per side
        const int bb2 = b - NB_WTK;
        const int side = bb2 / 384;
        const int rem = bb2 - side * 384;
        const int tr = rem >> 4, tc = rem & 15;    // 24 x 16
        transpose_tile(tile,
                       side ? W_pk2 : W_pk1,
                       side ? g_wtpk2_h : g_wtpk1_h,
                       side ? g_wtpk2_l : g_wtpk1_l,
                       CATD, AD, tr, tc);
        return;
    }
    if (b < NB_WTK + NB_WTPK + NB_VT) {
        // v transposes: src [SS, DV] -> [DV, SS]; 1024 tiles per batch, 16 batches
        const int bb2 = b - (NB_WTK + NB_WTPK);
        const int z = bb2 >> 10;                   // 0..15
        const int rem = bb2 & 1023;
        const int tr = rem >> 4, tc = rem & 15;    // 64 x 16
        const bool second = z >= BB;
        const long long batch = second ? (z - BB) : z;
        const float* src = (second ? v2 : v1) + batch * (long long)SS * DV;
        __nv_bfloat16* dh = (second ? g_vt2_h : g_vt1_h) + batch * (long long)DV * SS;
        __nv_bfloat16* dl = (second ? g_vt2_l : g_vt1_l) + batch * (long long)DV * SS;
        transpose_tile(tile, src, dh, dl, SS, DV, tr, tc);
        return;
    }

    // concat splits: [k | pk] fp32 -> hi/lo bf16 [Mtot, CATD]
    const int chunks = CATD / 4;                   // 192 per row
    const int Mtot = BB * SS;
    long long idx = (long long)(b - (NB_WTK + NB_WTPK + NB_VT)) * 256 + tid;
    const long long per_side = (long long)Mtot * chunks;
    const bool side2 = idx >= per_side;
    if (side2) idx -= per_side;
    const int r = (int)(idx / chunks);
    const int c = (int)(idx - (long long)r * chunks) * 4;

    const float* kk = side2 ? k2 : k1;
    const float* pp = side2 ? pk2c : pk1c;
    __nv_bfloat16* dh = side2 ? g_cat2_h : g_cat1_h;
    __nv_bfloat16* dl = side2 ? g_cat2_l : g_cat1_l;

    float4 v;
    if (c < KD) v = *(const float4*)(kk + (long long)r * KD + c);
    else        v = *(const float4*)(pp + (long long)r * PKD + (c - KD));

    __nv_bfloat16 h0, l0, h1, l1, h2, l2, h3, l3;
    split2(v.x, h0, l0); split2(v.y, h1, l1);
    split2(v.z, h2, l2); split2(v.w, h3, l3);
    long long base = (long long)r * CATD + c;
    *(uint2*)(dh + base) = make_uint2(pack_bf(h0, h1), pack_bf(h2, h3));
    *(uint2*)(dl + base) = make_uint2(pack_bf(l0, l1), pack_bf(l2, l3));
}

// ===========================================================================
// Masked in-place row softmax + fused bf16 split; both w matrices in one
// launch: blockIdx.y in [0,2*BB): y < BB -> w1 (lenR=l2,lenC=l1), else w2.
// ===========================================================================
__global__ __launch_bounds__(256) void softmax_mask_split_kernel(
    float* __restrict__ W1, float* __restrict__ W2,
    const int* __restrict__ l1, const int* __restrict__ l2)
{
    const int yraw = blockIdx.y;
    const bool second = yraw >= BB;
    const int b = second ? (yraw - BB) : yraw;
    float* W = second ? W2 : W1;
    __nv_bfloat16* Wh = second ? g_w2_h : g_w1_h;
    __nv_bfloat16* Wl = second ? g_w2_l : g_w1_l;
    const int* lenR = second ? l1 : l2;
    const int* lenC = second ? l2 : l1;

    const int r = blockIdx.x;
    const long long rowoff = ((long long)b * SS + r) * (long long)SS;
    float* row = W + rowoff;
    const int lc = read_len(lenC, b);
    const bool rover = r >= read_len(lenR, b);
    const int tid = threadIdx.x;
    const int c0 = tid * 8;

    float vals[8];
    float4 v0 = *(float4*)(row + c0);
    float4 v1 = *(float4*)(row + c0 + 4);
    vals[0] = v0.x; vals[1] = v0.y; vals[2] = v0.z; vals[3] = v0.w;
    vals[4] = v1.x; vals[5] = v1.y; vals[6] = v1.z; vals[7] = v1.w;

    float m = -CUDART_INF_F;
#pragma unroll
    for (int i = 0; i < 8; i++) {
        bool cover = (c0 + i) >= lc;
        if (cover != rover) vals[i] = -CUDART_INF_F;   // XOR mask semantics
        m = fmaxf(m, vals[i]);
    }

    const int lane = tid & 31, wrp = tid >> 5;
    __shared__ float smax[8];
    __shared__ float ssum[8];
#pragma unroll
    for (int o = 16; o; o >>= 1) m = fmaxf(m, __shfl_xor_sync(0xffffffffu, m, o));
    if (!lane) smax[wrp] = m;
    __syncthreads();
    m = smax[0];
#pragma unroll
    for (int i = 1; i < 8; i++) m = fmaxf(m, smax[i]);

    float s = 0.f;
#pragma unroll
    for (int i = 0; i < 8; i++) {
        vals[i] = __expf(vals[i] - m);
        s += vals[i];
    }
#pragma unroll
    for (int o = 16; o; o >>= 1) s += __shfl_xor_sync(0xffffffffu, s, o);
    if (!lane) ssum[wrp] = s;
    __syncthreads();
    s = ssum[0];
#pragma unroll
    for (int i = 1; i < 8; i++) s += ssum[i];
    const float inv = 1.f / s;

    uint32_t hiw[4], low[4];
#pragma unroll
    for (int i = 0; i < 8; i++) vals[i] *= inv;
#pragma unroll
    for (int j = 0; j < 4; j++) {
        __nv_bfloat16 h0, l0, h1, l1;
        split2(vals[2 * j + 0], h0, l0);
        split2(vals[2 * j + 1], h1, l1);
        hiw[j] = pack_bf(h0, h1);
        low[j] = pack_bf(l0, l1);
    }

    v0.x = vals[0]; v0.y = vals[1]; v0.z = vals[2]; v0.w = vals[3];
    v1.x = vals[4]; v1.y = vals[5]; v1.z = vals[6]; v1.w = vals[7];
    *(float4*)(row + c0) = v0;
    *(float4*)(row + c0 + 4) = v1;
    *(uint4*)(Wh + rowoff + c0) = make_uint4(hiw[0], hiw[1], hiw[2], hiw[3]);
    *(uint4*)(Wl + rowoff + c0) = make_uint4(low[0], low[1], low[2], low[3]);
}

// ===========================================================================
// Launch
// ===========================================================================
extern "C" void kernel_launch(void* const* d_in, const int* in_sizes, int n_in,
                              void* d_out, int out_size)
{
    const float* k1   = (const float*)d_in[0];
    const float* k2   = (const float*)d_in[1];
    const float* pk1c = (const float*)d_in[2];
    const float* pk2c = (const float*)d_in[3];
    const float* v1   = (const float*)d_in[4];
    const float* v2   = (const float*)d_in[5];
    const float* W_k1  = (const float*)d_in[6];
    const float* b_k1  = (const float*)d_in[7];
    const float* W_k2  = (const float*)d_in[8];
    const float* b_k2  = (const float*)d_in[9];
    const float* W_pk1 = (const float*)d_in[10];
    const float* b_pk1 = (const float*)d_in[11];
    const float* W_pk2 = (const float*)d_in[12];
    const float* b_pk2 = (const float*)d_in[13];
    const int* l1 = (const int*)d_in[14];
    const int* l2 = (const int*)d_in[15];

    float* o1 = (float*)d_out;                               // [B,S2,DV]
    float* o2 = o1 + (long long)BB * SS * DV;                // [B,S1,DV]
    float* w1 = o2 + (long long)BB * SS * DV;                // [B,S2,S1]
    float* w2 = w1 + (long long)BB * SS * SS;                // [B,S1,S2]

    __nv_bfloat16 *cat1h, *cat1l, *cat2h, *cat2l;
    __nv_bfloat16 *k1ph, *k1pl, *k2ph, *k2pl, *pk1h, *pk1l, *pk2h, *pk2l;
    __nv_bfloat16 *wtk1h, *wtk1l, *wtk2h, *wtk2l, *wtpk1h, *wtpk1l, *wtpk2h, *wtpk2l;
    __nv_bfloat16 *vt1h, *vt1l, *vt2h, *vt2l;
    __nv_bfloat16 *w1h, *w1l, *w2h, *w2l;
    cudaGetSymbolAddress((void**)&cat1h, g_cat1_h); cudaGetSymbolAddress((void**)&cat1l, g_cat1_l);
    cudaGetSymbolAddress((void**)&cat2h, g_cat2_h); cudaGetSymbolAddress((void**)&cat2l, g_cat2_l);
    cudaGetSymbolAddress((void**)&k1ph, g_k1p_h);   cudaGetSymbolAddress((void**)&k1pl, g_k1p_l);
    cudaGetSymbolAddress((void**)&k2ph, g_k2p_h);   cudaGetSymbolAddress((void**)&k2pl, g_k2p_l);
    cudaGetSymbolAddress((void**)&pk1h, g_pk1_h);   cudaGetSymbolAddress((void**)&pk1l, g_pk1_l);
    cudaGetSymbolAddress((void**)&pk2h, g_pk2_h);   cudaGetSymbolAddress((void**)&pk2l, g_pk2_l);
    cudaGetSymbolAddress((void**)&wtk1h, g_wtk1_h); cudaGetSymbolAddress((void**)&wtk1l, g_wtk1_l);
    cudaGetSymbolAddress((void**)&wtk2h, g_wtk2_h); cudaGetSymbolAddress((void**)&wtk2l, g_wtk2_l);
    cudaGetSymbolAddress((void**)&wtpk1h, g_wtpk1_h); cudaGetSymbolAddress((void**)&wtpk1l, g_wtpk1_l);
    cudaGetSymbolAddress((void**)&wtpk2h, g_wtpk2_h); cudaGetSymbolAddress((void**)&wtpk2l, g_wtpk2_l);
    cudaGetSymbolAddress((void**)&vt1h, g_vt1_h);   cudaGetSymbolAddress((void**)&vt1l, g_vt1_l);
    cudaGetSymbolAddress((void**)&vt2h, g_vt2_h);   cudaGetSymbolAddress((void**)&vt2l, g_vt2_l);
    cudaGetSymbolAddress((void**)&w1h, g_w1_h);     cudaGetSymbolAddress((void**)&w1l, g_w1_l);
    cudaGetSymbolAddress((void**)&w2h, g_w2_h);     cudaGetSymbolAddress((void**)&w2l, g_w2_l);

    cudaFuncSetAttribute(gemm_nt_mma,
                         cudaFuncAttributeMaxDynamicSharedMemorySize, SMEM_GEMM);

    const int Mtot = BB * SS;   // 16384

    // (1) ALL preprocessing in one launch
    prep_kernel<<<NB_PREP, 256>>>(k1, pk1c, k2, pk2c, v1, v2,
                                  W_k1, W_k2, W_pk1, W_pk2);

    // (2) k-projection GEMMs merged (z=2): k1p, k2p
    gemm_nt_mma<<<dim3(AD / GBN, Mtot / GBM, 2), 256, SMEM_GEMM>>>(
        cat1h, cat1l, wtk1h, wtk1l, nullptr, k1ph, k1pl, b_k1,
        cat2h, cat2l, wtk2h, wtk2l, nullptr, k2ph, k2pl, b_k2,
        1, CATD, 0, KD, 0, KD, 0, AD, 1);
    // (3) pk-projection GEMMs merged (z=2): pk1, pk2
    gemm_nt_mma<<<dim3(AD / GBN, Mtot / GBM, 2), 256, SMEM_GEMM>>>(
        cat1h, cat1l, wtpk1h, wtpk1l, nullptr, pk1h, pk1l, b_pk1,
        cat2h, cat2l, wtpk2h, wtpk2l, nullptr, pk2h, pk2l, b_pk2,
        1, CATD, 0, CATD, 0, CATD, 0, AD, 1);

    // (4) score GEMMs merged (z=16, fp32 into w regions)
    //     w1_pre[t,s] = pk2[t,:].k1p[s,:]   w2_pre[s,t] = pk1[s,:].k2p[t,:]
    gemm_nt_mma<<<dim3(SS / GBN, SS / GBM, 2 * BB), 256, SMEM_GEMM>>>(
        pk2h, pk2l, k1ph, k1pl, w1, nullptr, nullptr, nullptr,
        pk1h, pk1l, k2ph, k2pl, w2, nullptr, nullptr, nullptr,
        BB, AD, (long long)SS * AD, AD, (long long)SS * AD,
        AD, (long long)SS * SS, SS, 0);

    // (5) masked softmax + split, both w matrices (grid.y = 16)
    softmax_mask_split_kernel<<<dim3(SS, 2 * BB), 256>>>(w1, w2, l1, l2);

    // (6) output GEMMs merged (z=16): o1 = w1 @ v1, o2 = w2 @ v2
    gemm_nt_mma<<<dim3(DV / GBN, SS / GBM, 2 * BB), 256, SMEM_GEMM>>>(
        w1h, w1l, vt1h, vt1l, o1, nullptr, nullptr, nullptr,
        w2h, w2l, vt2h, vt2l, o2, nullptr, nullptr, nullptr,
        BB, SS, (long long)SS * SS, SS, (long long)DV * SS,
        SS, (long long)SS * DV, DV, 0);
}